// round 15
// baseline (speedup 1.0000x reference)
#include <cuda_runtime.h>
#include <cstdint>
#include <math.h>

#define NB 4
#define DIMC 256
#define HH 64
#define WW 64
#define NPOS (HH*WW)
#define NHEAD 4
#define HD 64

// ---------------- scratch ----------------
__device__ float g_qt[NB*NPOS*DIMC];         // LN(q)*scale, tf32-rounded [b][n][o]
__device__ float g_kctx[NB*49*DIMC];         // pooled ctx, tf32-rounded
__device__ float g_kraw[256*DIMC];           // Wk@kctx raw fp32 (196 rows used)
__device__ float2 g_kpart[2][256];           // per-n-half row partials (sum, sum2)
__device__ float g_kfp[NB*NHEAD*80*64];      // folded proj, tf32-rounded [bg][m pad80][c]
__device__ float g_attn[NB*NHEAD*NPOS*52];   // softmaxed attn
__device__ float g_mid[NB*NPOS*DIMC];        // AV out, tf32-rounded [b][n][c]
__device__ float g_wqtf[DIMC*DIMC];          // tf32-rounded weights
__device__ float g_wktf[DIMC*DIMC];
__device__ float g_wdytf[DIMC*DIMC];

__device__ __forceinline__ void cvt_tf32(uint32_t& r) {
    asm("cvt.rna.tf32.f32 %0, %0;" : "+r"(r));
}
__device__ __forceinline__ float rnd_tf32(float f) {
    uint32_t r; asm("cvt.rna.tf32.f32 %0, %1;" : "=r"(r) : "f"(f));
    return __uint_as_float(r);
}
__device__ __forceinline__ void cp16(uint32_t saddr, const void* gaddr) {
    asm volatile("cp.async.ca.shared.global [%0], [%1], 16;" :: "r"(saddr), "l"(gaddr));
}
#define CP_COMMIT() asm volatile("cp.async.commit_group;" ::: "memory")
#define CP_WAIT1()  asm volatile("cp.async.wait_group 1;" ::: "memory")
#define CP_WAIT0()  asm volatile("cp.async.wait_group 0;" ::: "memory")

// ---------------- weight pre-convert ----------------
__global__ __launch_bounds__(256) void wconv_kernel(const float* __restrict__ Wq,
                                                    const float* __restrict__ Wk,
                                                    const float* __restrict__ Wdy) {
    int idx = blockIdx.x * 256 + threadIdx.x;
    g_wqtf[idx]  = rnd_tf32(Wq[idx]);
    g_wktf[idx]  = rnd_tf32(Wk[idx]);
    g_wdytf[idx] = rnd_tf32(Wdy[idx]);
}

// ================= gemm1 + fused LN (cp.async double-buffered) =================
#define ASTR 136
#define G1WORDS (32*ASTR + 256*36)     // words per buffer
__global__ __launch_bounds__(512, 1)
void gemm1_ln_kernel(const float* __restrict__ x, const float* __restrict__ Wq,
                     const float* __restrict__ gq, const float* __restrict__ bq) {
    extern __shared__ uint32_t sm[];                 // 2 x (As2[32*ASTR] ++ Bs[256*36])
    __shared__ float red_s[128][9];
    __shared__ float red_s2[128][9];
    __shared__ float sg[256], sb[256];

    int tid  = threadIdx.x;
    int wid  = tid >> 5, lane = tid & 31;
    int q    = lane >> 2, tq = lane & 3;
    int wm   = wid >> 3, wn = wid & 7;               // 2 x 8
    int z    = blockIdx.z;
    int m0   = blockIdx.x * 128;
    const float* xb = x + (size_t)z * DIMC * NPOS;
    uint32_t sbase = (uint32_t)__cvta_generic_to_shared(sm);

    if (tid < 256) { sg[tid] = gq[tid]; sb[tid] = bq[tid]; }

    float c[4][4][4];
#pragma unroll
    for (int mt = 0; mt < 4; mt++)
#pragma unroll
        for (int nt = 0; nt < 4; nt++)
#pragma unroll
            for (int i = 0; i < 4; i++) c[mt][nt][i] = 0.f;

    auto issue = [&](int ck, int s) {
        uint32_t abase = sbase + (uint32_t)(s * G1WORDS) * 4u;
        uint32_t bbase = abase + 32u * ASTR * 4u;
#pragma unroll
        for (int it = 0; it < 2; it++) {
            int slot = tid + it * 512;
            int cc = slot >> 5, n4 = slot & 31;
            cp16(abase + (uint32_t)(cc * ASTR + n4 * 4) * 4u,
                 xb + (size_t)(ck * 32 + cc) * NPOS + m0 + n4 * 4);
        }
#pragma unroll
        for (int it = 0; it < 4; it++) {
            int slot = tid + it * 512;
            int row = slot >> 3, c4 = slot & 7;
            cp16(bbase + (uint32_t)(row * 36 + c4 * 4) * 4u,
                 Wq + (size_t)row * DIMC + ck * 32 + c4 * 4);
        }
        CP_COMMIT();
    };

    issue(0, 0);
    for (int ck = 0; ck < 8; ck++) {
        int s = ck & 1;
        if (ck < 7) { issue(ck + 1, s ^ 1); CP_WAIT1(); }
        else        { CP_WAIT0(); }
        __syncthreads();
        const uint32_t* As2 = sm + s * G1WORDS;
        const uint32_t* Bs  = As2 + 32 * ASTR;
#pragma unroll
        for (int ks = 0; ks < 4; ks++) {
            int k0 = ks * 8;
            uint32_t a[4][4];
#pragma unroll
            for (int mt = 0; mt < 4; mt++) {
                int r = wm * 64 + mt * 16 + q;
                a[mt][0] = As2[(k0 + tq) * ASTR + r];
                a[mt][1] = As2[(k0 + tq) * ASTR + r + 8];
                a[mt][2] = As2[(k0 + tq + 4) * ASTR + r];
                a[mt][3] = As2[(k0 + tq + 4) * ASTR + r + 8];
                cvt_tf32(a[mt][0]); cvt_tf32(a[mt][1]); cvt_tf32(a[mt][2]); cvt_tf32(a[mt][3]);
            }
            uint32_t b[4][2];
#pragma unroll
            for (int nt = 0; nt < 4; nt++) {
                int o = wn * 32 + nt * 8 + q;
                b[nt][0] = Bs[o * 36 + k0 + tq];
                b[nt][1] = Bs[o * 36 + k0 + tq + 4];
            }
#pragma unroll
            for (int mt = 0; mt < 4; mt++)
#pragma unroll
                for (int nt = 0; nt < 4; nt++) {
                    asm volatile(
                        "mma.sync.aligned.m16n8k8.row.col.f32.tf32.tf32.f32 "
                        "{%0,%1,%2,%3}, {%4,%5,%6,%7}, {%8,%9}, {%0,%1,%2,%3};"
                        : "+f"(c[mt][nt][0]), "+f"(c[mt][nt][1]),
                          "+f"(c[mt][nt][2]), "+f"(c[mt][nt][3])
                        : "r"(a[mt][0]), "r"(a[mt][1]), "r"(a[mt][2]), "r"(a[mt][3]),
                          "r"(b[nt][0]), "r"(b[nt][1]));
                }
        }
        __syncthreads();
    }

    // ---- fused LN epilogue ----
#pragma unroll
    for (int mt = 0; mt < 4; mt++) {
#pragma unroll
        for (int h = 0; h < 2; h++) {
            float s = 0.f, s2 = 0.f;
#pragma unroll
            for (int nt = 0; nt < 4; nt++) {
                float v0 = c[mt][nt][2*h], v1 = c[mt][nt][2*h+1];
                s += v0 + v1; s2 += v0*v0 + v1*v1;
            }
            s  += __shfl_xor_sync(0xffffffffu, s, 1);
            s2 += __shfl_xor_sync(0xffffffffu, s2, 1);
            s  += __shfl_xor_sync(0xffffffffu, s, 2);
            s2 += __shfl_xor_sync(0xffffffffu, s2, 2);
            if (tq == 0) {
                int rl = wm * 64 + mt * 16 + q + h * 8;
                red_s[rl][wn] = s;
                red_s2[rl][wn] = s2;
            }
        }
    }
    __syncthreads();
    float* outb = g_qt + (size_t)z * NPOS * DIMC;
#pragma unroll
    for (int mt = 0; mt < 4; mt++) {
#pragma unroll
        for (int h = 0; h < 2; h++) {
            int rl = wm * 64 + mt * 16 + q + h * 8;
            float S = 0.f, S2 = 0.f;
#pragma unroll
            for (int w = 0; w < 8; w++) { S += red_s[rl][w]; S2 += red_s2[rl][w]; }
            float mu = S * (1.f/256.f);
            float var = S2 * (1.f/256.f) - mu * mu;
            float rs = rsqrtf(var + 1e-6f);
            float* rowp = outb + (size_t)(m0 + rl) * DIMC;
#pragma unroll
            for (int nt = 0; nt < 4; nt++) {
                int o = wn * 32 + nt * 8 + 2 * tq;
                float2 v;
                v.x = rnd_tf32(((c[mt][nt][2*h]   - mu) * rs * sg[o]   + sb[o])   * 0.125f);
                v.y = rnd_tf32(((c[mt][nt][2*h+1] - mu) * rs * sg[o+1] + sb[o+1]) * 0.125f);
                *(float2*)(rowp + o) = v;
            }
        }
    }
}

// ================= generic mma.sync tf32 GEMM (cp.async, cvt-free) =================
// EPI 0: raw store + per-row partial stats -> g_kpart[blockIdx.y]  (kf GEMM only)
// EPI 1: BN + transposed store
#define GWORDS (2 * 128 * 36)
template<int EPI>
__global__ __launch_bounds__(256, 2)
void mma_gemm_kernel(const float* __restrict__ A, const float* __restrict__ B,
                     float* __restrict__ Out, const float* __restrict__ p1,
                     const float* __restrict__ p2, int mvalid, int batchStride) {
    extern __shared__ uint32_t sm[];
    __shared__ float sp1[256], sp2[256];
    __shared__ float prs[128][4], prs2[128][4];    // EPI 0 stat partials

    int tid = threadIdx.x;
    int wid = tid >> 5;
    int lane = tid & 31;
    int q = lane >> 2, tq = lane & 3;
    int wm = wid >> 2, wn = wid & 3;
    int z = blockIdx.z;
    int m0 = blockIdx.x * 128;
    int n0 = blockIdx.y * 128;
    const float* Ab = A + (size_t)z * batchStride;
    uint32_t sbase = (uint32_t)__cvta_generic_to_shared(sm);

    if (EPI == 1) { sp1[tid] = p1[tid] * rsqrtf(1.f + 1e-5f); sp2[tid] = p2[tid]; }

    float c[4][4][4];
#pragma unroll
    for (int mt = 0; mt < 4; mt++)
#pragma unroll
        for (int nt = 0; nt < 4; nt++)
#pragma unroll
            for (int i = 0; i < 4; i++) c[mt][nt][i] = 0.f;

    auto issue = [&](int ck, int s) {
        uint32_t abase = sbase + (uint32_t)(s * GWORDS) * 4u;
        uint32_t bbase = abase + 128u * 36u * 4u;
#pragma unroll
        for (int t = 0; t < 4; t++) {
            int idx = tid + t * 256;
            int row = idx >> 3, c4 = idx & 7;
            int ga = min(m0 + row, mvalid - 1);
            cp16(abase + (uint32_t)(row * 36 + c4 * 4) * 4u,
                 Ab + (size_t)ga * DIMC + ck * 32 + c4 * 4);
            cp16(bbase + (uint32_t)(row * 36 + c4 * 4) * 4u,
                 B + (size_t)(n0 + row) * DIMC + ck * 32 + c4 * 4);
        }
        CP_COMMIT();
    };

    issue(0, 0);
    for (int ck = 0; ck < 8; ck++) {
        int s = ck & 1;
        if (ck < 7) { issue(ck + 1, s ^ 1); CP_WAIT1(); }
        else        { CP_WAIT0(); }
        __syncthreads();
        const uint32_t* As = sm + s * GWORDS;
        const uint32_t* Bs = As + 128 * 36;
#pragma unroll
        for (int ks = 0; ks < 4; ks++) {
            int k0 = ks * 8;
            uint32_t a[4][4];
#pragma unroll
            for (int mt = 0; mt < 4; mt++) {
                int r = wm * 64 + mt * 16 + q;
                a[mt][0] = As[r * 36 + k0 + tq];
                a[mt][1] = As[(r + 8) * 36 + k0 + tq];
                a[mt][2] = As[r * 36 + k0 + tq + 4];
                a[mt][3] = As[(r + 8) * 36 + k0 + tq + 4];
            }
            uint32_t b[4][2];
#pragma unroll
            for (int nt = 0; nt < 4; nt++) {
                int nn = wn * 32 + nt * 8 + q;
                b[nt][0] = Bs[nn * 36 + k0 + tq];
                b[nt][1] = Bs[nn * 36 + k0 + tq + 4];
            }
#pragma unroll
            for (int mt = 0; mt < 4; mt++)
#pragma unroll
                for (int nt = 0; nt < 4; nt++) {
                    asm volatile(
                        "mma.sync.aligned.m16n8k8.row.col.f32.tf32.tf32.f32 "
                        "{%0,%1,%2,%3}, {%4,%5,%6,%7}, {%8,%9}, {%0,%1,%2,%3};"
                        : "+f"(c[mt][nt][0]), "+f"(c[mt][nt][1]),
                          "+f"(c[mt][nt][2]), "+f"(c[mt][nt][3])
                        : "r"(a[mt][0]), "r"(a[mt][1]), "r"(a[mt][2]), "r"(a[mt][3]),
                          "r"(b[nt][0]), "r"(b[nt][1]));
                }
        }
        __syncthreads();
    }

#pragma unroll
    for (int mt = 0; mt < 4; mt++) {
        int r0 = m0 + wm * 64 + mt * 16 + q;
#pragma unroll
        for (int nt = 0; nt < 4; nt++) {
            int o0 = n0 + wn * 32 + nt * 8 + 2 * tq;
            if (EPI == 0) {
                if (r0 < mvalid) {
                    float2 v = make_float2(c[mt][nt][0], c[mt][nt][1]);
                    *(float2*)(Out + (size_t)(z * NPOS + r0) * DIMC + o0) = v;
                }
                if (r0 + 8 < mvalid) {
                    float2 v = make_float2(c[mt][nt][2], c[mt][nt][3]);
                    *(float2*)(Out + (size_t)(z * NPOS + r0 + 8) * DIMC + o0) = v;
                }
            } else {
                float s0 = sp1[o0],     h0 = sp2[o0];
                float s1 = sp1[o0 + 1], h1 = sp2[o0 + 1];
                float* base0 = Out + ((size_t)(z * DIMC + o0)) * NPOS;
                float* base1 = Out + ((size_t)(z * DIMC + o0 + 1)) * NPOS;
                base0[r0]     = c[mt][nt][0] * s0 + h0;
                base1[r0]     = c[mt][nt][1] * s1 + h1;
                base0[r0 + 8] = c[mt][nt][2] * s0 + h0;
                base1[r0 + 8] = c[mt][nt][3] * s1 + h1;
            }
        }
    }

    if (EPI == 0) {
        // per-row partial stats over this block's 128 cols
#pragma unroll
        for (int mt = 0; mt < 4; mt++) {
#pragma unroll
            for (int h = 0; h < 2; h++) {
                float s = 0.f, s2 = 0.f;
#pragma unroll
                for (int nt = 0; nt < 4; nt++) {
                    float v0 = c[mt][nt][2*h], v1 = c[mt][nt][2*h+1];
                    s += v0 + v1; s2 += v0*v0 + v1*v1;
                }
                s  += __shfl_xor_sync(0xffffffffu, s, 1);
                s2 += __shfl_xor_sync(0xffffffffu, s2, 1);
                s  += __shfl_xor_sync(0xffffffffu, s, 2);
                s2 += __shfl_xor_sync(0xffffffffu, s2, 2);
                if (tq == 0) {
                    int rl = wm * 64 + mt * 16 + q + h * 8;
                    prs[rl][wn]  = s;
                    prs2[rl][wn] = s2;
                }
            }
        }
        __syncthreads();
        if (tid < 128) {
            float S  = prs[tid][0]  + prs[tid][1]  + prs[tid][2]  + prs[tid][3];
            float S2 = prs2[tid][0] + prs2[tid][1] + prs2[tid][2] + prs2[tid][3];
            g_kpart[blockIdx.y][m0 + tid] = make_float2(S, S2);
        }
    }
}

// ---------------- ctx 8x8 avg pool (warp-per-channel, tf32-rounded out) ----------------
__global__ __launch_bounds__(256) void pool_kernel(const float* __restrict__ ctx) {
    int l = blockIdx.x, b = blockIdx.y;
    int li = l / 7, lj = l % 7;
    int wid = threadIdx.x >> 5, lane = threadIdx.x & 31;
    int ri = lane >> 2, rj = lane & 3;
    const float* base = ctx + (size_t)b * DIMC * 3136 + (li * 8 + ri) * 56 + lj * 8 + rj * 2;
    float* outp = g_kctx + (size_t)(b * 49 + l) * DIMC;
#pragma unroll
    for (int k = 0; k < 32; k++) {
        int c = wid * 32 + k;
        float2 v = *(const float2*)(base + (size_t)c * 3136);
        float s = v.x + v.y;
#pragma unroll
        for (int o = 16; o >= 1; o >>= 1) s += __shfl_xor_sync(0xffffffffu, s, o);
        if (lane == 0) outp[c] = rnd_tf32(s * (1.f / 64.f));
    }
}

// ---------------- fold Wproj -> kfp[bg][m][c], grid (16 bg, 5 mg); stats precomputed ----------------
__global__ __launch_bounds__(256) void kfp_kernel(const float* __restrict__ Wproj,
                                                  const float* __restrict__ gk,
                                                  const float* __restrict__ bk) {
    __shared__ float smu[49], srs[49];
    __shared__ float sn[49 * 64];
    __shared__ float swp[16 * 49];
    int bg = blockIdx.x;
    int mg = blockIdx.y;                 // 0..4 -> m in [mg*16, mg*16+16)
    int b = bg >> 2, gg = bg & 3;
    int tid = threadIdx.x;

    if (tid < 49) {
        int row = b * 49 + tid;
        float2 p0 = g_kpart[0][row];
        float2 p1 = g_kpart[1][row];
        float S  = p0.x + p1.x;
        float S2 = p0.y + p1.y;
        float mu = S * (1.f / DIMC);
        float var = S2 * (1.f / DIMC) - mu * mu;
        smu[tid] = mu;
        srs[tid] = rsqrtf(var + 1e-6f);
    }
    for (int idx = tid; idx < 16 * 49; idx += 256) {
        int m = mg * 16 + idx / 49;
        swp[idx] = (m < 74) ? Wproj[m * 49 + (idx % 49)] : 0.f;
    }
    __syncthreads();
    for (int idx = tid; idx < 49 * 64; idx += 256) {
        int l = idx >> 6, c = idx & 63;
        sn[idx] = (g_kraw[(size_t)(b * 49 + l) * DIMC + gg * HD + c] - smu[l]) * srs[l];
    }
    __syncthreads();

    int c = tid & 63, mb = tid >> 6;     // mb 0..3, 4 m per thread
    float gkv = gk[gg * HD + c], bkv = bk[gg * HD + c];
    float* outp = g_kfp + (size_t)bg * 80 * 64;
    float acc[4] = {0.f, 0.f, 0.f, 0.f};
    float sw[4]  = {0.f, 0.f, 0.f, 0.f};
    for (int l = 0; l < 49; l++) {
        float v = sn[l * 64 + c];
#pragma unroll
        for (int mm = 0; mm < 4; mm++) {
            float w = swp[(mb * 4 + mm) * 49 + l];
            acc[mm] += v * w;
            sw[mm]  += w;
        }
    }
#pragma unroll
    for (int mm = 0; mm < 4; mm++) {
        int m = mg * 16 + mb * 4 + mm;
        outp[m * 64 + c] = (m < 74) ? rnd_tf32(acc[mm] * gkv + sw[mm] * bkv) : 0.f;
    }
}

// ---------------- wgt mma GEMM [128 x 80 x 64] + RPB + softmax (cvt-free) ----------------
__global__ __launch_bounds__(256)
void wgt_mma_kernel(const float* __restrict__ rpb1, const float* __restrict__ rpb2) {
    extern __shared__ char smc[];
    uint32_t* As = (uint32_t*)smc;                 // [128][68]
    uint32_t* Bs = As + 128 * 68;                  // [80][68]
    float*    Wg = (float*)smc;                    // [128][85]
    __shared__ float srpb[169];

    int tid = threadIdx.x;
    int wid = tid >> 5, lane = tid & 31;
    int q = lane >> 2, tq = lane & 3;
    int wm = wid >> 1, wn = wid & 1;
    int m0 = blockIdx.x * 128;
    int gy = blockIdx.y;
    int b  = gy >> 2, g = gy & 3;

    if (g < 2) { if (tid < 81) srpb[tid] = rpb1[g*81 + tid]; }
    else       { if (tid < 169) srpb[tid] = rpb2[(g-2)*169 + tid]; }

    const float* Abase = g_qt + ((size_t)(b * NPOS + m0)) * DIMC + g * HD;
#pragma unroll
    for (int it = 0; it < 8; it++) {
        int slot = tid + it * 256;
        int row = slot >> 4, c4 = slot & 15;
        uint4 u = *(const uint4*)(Abase + (size_t)row * DIMC + c4 * 4);
        *(uint4*)(As + row * 68 + c4 * 4) = u;
    }
    const float* Bbase = g_kfp + (size_t)gy * 80 * 64;
#pragma unroll
    for (int it = 0; it < 5; it++) {
        int slot = tid + it * 256;
        int mrow = slot >> 4, c4 = slot & 15;
        uint4 u = *(const uint4*)(Bbase + (size_t)mrow * 64 + c4 * 4);
        *(uint4*)(Bs + mrow * 68 + c4 * 4) = u;
    }
    __syncthreads();

    float c[2][5][4];
#pragma unroll
    for (int mt = 0; mt < 2; mt++)
#pragma unroll
        for (int nt = 0; nt < 5; nt++)
#pragma unroll
            for (int i = 0; i < 4; i++) c[mt][nt][i] = 0.f;

#pragma unroll
    for (int ks = 0; ks < 8; ks++) {
        int k0 = ks * 8;
        uint32_t a[2][4];
#pragma unroll
        for (int mt = 0; mt < 2; mt++) {
            int r = wm * 32 + mt * 16 + q;
            a[mt][0] = As[r * 68 + k0 + tq];
            a[mt][1] = As[(r + 8) * 68 + k0 + tq];
            a[mt][2] = As[r * 68 + k0 + tq + 4];
            a[mt][3] = As[(r + 8) * 68 + k0 + tq + 4];
        }
        uint32_t bfr[5][2];
#pragma unroll
        for (int nt = 0; nt < 5; nt++) {
            int col = wn * 40 + nt * 8 + q;
            bfr[nt][0] = Bs[col * 68 + k0 + tq];
            bfr[nt][1] = Bs[col * 68 + k0 + tq + 4];
        }
#pragma unroll
        for (int mt = 0; mt < 2; mt++)
#pragma unroll
            for (int nt = 0; nt < 5; nt++) {
                asm volatile(
                    "mma.sync.aligned.m16n8k8.row.col.f32.tf32.tf32.f32 "
                    "{%0,%1,%2,%3}, {%4,%5,%6,%7}, {%8,%9}, {%0,%1,%2,%3};"
                    : "+f"(c[mt][nt][0]), "+f"(c[mt][nt][1]),
                      "+f"(c[mt][nt][2]), "+f"(c[mt][nt][3])
                    : "r"(a[mt][0]), "r"(a[mt][1]), "r"(a[mt][2]), "r"(a[mt][3]),
                      "r"(bfr[nt][0]), "r"(bfr[nt][1]));
            }
    }
    __syncthreads();

#pragma unroll
    for (int mt = 0; mt < 2; mt++) {
        int r = wm * 32 + mt * 16 + q;
#pragma unroll
        for (int nt = 0; nt < 5; nt++) {
            int col = wn * 40 + nt * 8 + 2 * tq;
            Wg[r * 85 + col]       = c[mt][nt][0];
            Wg[r * 85 + col + 1]   = c[mt][nt][1];
            Wg[(r+8) * 85 + col]   = c[mt][nt][2];
            Wg[(r+8) * 85 + col+1] = c[mt][nt][3];
        }
    }
    __syncthreads();

    if (tid < 128) {
        int n = m0 + tid;
        int i = n >> 6, j = n & 63;
        float* wrow = Wg + tid * 85;
        float* arow = g_attn + ((size_t)(gy * NPOS + n)) * 52;
        if (g < 2) {
            int si = min(max(i-2,0),HH-5), sj = min(max(j-2,0),WW-5);
            int bi = 4 - (i - si), bj = 4 - (j - sj);
            float mx = -1e30f;
#pragma unroll
            for (int m = 0; m < 25; m++) {
                int p = m / 5, qq = m - p*5;
                float v = wrow[m] + srpb[(bi+p)*9 + bj + qq];
                wrow[m] = v;
                mx = fmaxf(mx, v);
            }
            float sum = 0.f;
#pragma unroll
            for (int m = 0; m < 25; m++) {
                float e = __expf(wrow[m] - mx);
                wrow[m] = e; sum += e;
            }
            float inv = 1.f / sum;
#pragma unroll
            for (int m = 0; m < 25; m++) arow[m] = wrow[m] * inv;
        } else {
            int si = min(max(i-3,0),HH-7), sj = min(max(j-3,0),WW-7);
            int bi = 6 - (i - si), bj = 6 - (j - sj);
            float mx = -1e30f;
#pragma unroll
            for (int t = 0; t < 49; t++) {
                int p = t / 7, qq = t - p*7;
                float v = wrow[25 + t] + srpb[(bi+p)*13 + bj + qq];
                wrow[25 + t] = v;
                mx = fmaxf(mx, v);
            }
            float sum = 0.f;
#pragma unroll
            for (int t = 0; t < 49; t++) {
                float e = __expf(wrow[25 + t] - mx);
                wrow[25 + t] = e; sum += e;
            }
            float inv = 1.f / sum;
#pragma unroll
            for (int t = 0; t < 49; t++) arow[t] = wrow[25 + t] * inv;
        }
    }
}

// ---------------- neighborhood AV (pixel-paired, tf32-rounded out) ----------------
template<int KK>
__device__ __forceinline__ void av_body(const float* __restrict__ x, int g, float* vs) {
    const int HALO = 8 + KK - 1;
    int ti0 = (blockIdx.x >> 3) * 8, tj0 = (blockIdx.x & 7) * 8;
    int b = blockIdx.z;
    int hbi = min(max(ti0 - KK/2, 0), HH - HALO);
    int hbj = min(max(tj0 - KK/2, 0), WW - HALO);
    const float* xb = x + (size_t)(b*DIMC + g*HD)*NPOS;
    for (int idx = threadIdx.x; idx < HALO*HALO*HD; idx += 256) {
        int c  = idx / (HALO*HALO);
        int rr = idx - c*HALO*HALO;
        int ri = rr / HALO, rj = rr - ri*HALO;
        vs[rr*68 + c] = xb[(size_t)c*NPOS + (hbi+ri)*WW + hbj + rj];
    }
    __syncthreads();
    int t = threadIdx.x;
    int pairIdx = t >> 3, cg = t & 7;
    int i  = ti0 + (pairIdx >> 2);
    int j0 = tj0 + (pairIdx & 3) * 2;
    int si  = min(max(i  - KK/2, 0), HH-KK) - hbi;
    int sj0 = min(max(j0     - KK/2, 0), WW-KK) - hbj;
    int sj1 = min(max(j0 + 1 - KK/2, 0), WW-KK) - hbj;
    int off1 = sj1 - sj0;
    int n0 = i*WW + j0;
    const float* ar0 = g_attn + ((size_t)((b*NHEAD+g)*NPOS + n0))*52;
    const float* ar1 = ar0 + 52;
    float4 p0a = make_float4(0,0,0,0), p0b = p0a, p1a = p0a, p1b = p0a;
    int qend = KK + off1;
#pragma unroll
    for (int p = 0; p < KK; p++) {
        const float* aw0 = ar0 + p*KK;
        const float* aw1 = ar1 + p*KK - off1;
        const float* vrow = &vs[((si+p)*HALO + sj0)*68 + cg*8];
        for (int q = 0; q < qend; q++) {
            const float4* vp = reinterpret_cast<const float4*>(vrow + q*68);
            float4 v0 = vp[0], v1 = vp[1];
            float w0 = (q < KK) ? __ldg(aw0 + q) : 0.f;
            float w1 = (q >= off1) ? __ldg(aw1 + q) : 0.f;
            p0a.x += w0*v0.x; p0a.y += w0*v0.y; p0a.z += w0*v0.z; p0a.w += w0*v0.w;
            p0b.x += w0*v1.x; p0b.y += w0*v1.y; p0b.z += w0*v1.z; p0b.w += w0*v1.w;
            p1a.x += w1*v0.x; p1a.y += w1*v0.y; p1a.z += w1*v0.z; p1a.w += w1*v0.w;
            p1b.x += w1*v1.x; p1b.y += w1*v1.y; p1b.z += w1*v1.z; p1b.w += w1*v1.w;
        }
    }
    p0a.x = rnd_tf32(p0a.x); p0a.y = rnd_tf32(p0a.y); p0a.z = rnd_tf32(p0a.z); p0a.w = rnd_tf32(p0a.w);
    p0b.x = rnd_tf32(p0b.x); p0b.y = rnd_tf32(p0b.y); p0b.z = rnd_tf32(p0b.z); p0b.w = rnd_tf32(p0b.w);
    p1a.x = rnd_tf32(p1a.x); p1a.y = rnd_tf32(p1a.y); p1a.z = rnd_tf32(p1a.z); p1a.w = rnd_tf32(p1a.w);
    p1b.x = rnd_tf32(p1b.x); p1b.y = rnd_tf32(p1b.y); p1b.z = rnd_tf32(p1b.z); p1b.w = rnd_tf32(p1b.w);
    float* op0 = g_mid + ((size_t)(b*NPOS + n0))*DIMC + g*HD + cg*8;
    float* op1 = op0 + DIMC;
    ((float4*)op0)[0] = p0a; ((float4*)op0)[1] = p0b;
    ((float4*)op1)[0] = p1a; ((float4*)op1)[1] = p1b;
}

__global__ __launch_bounds__(256) void av_all_kernel(const float* __restrict__ x) {
    extern __shared__ float vs[];
    int g = blockIdx.y;
    if (g < 2) av_body<5>(x, g, vs);
    else       av_body<7>(x, g, vs);
}

extern "C" void kernel_launch(void* const* d_in, const int* in_sizes, int n_in,
                              void* d_out, int out_size) {
    const float* x     = (const float*)d_in[0];
    const float* ctx   = (const float*)d_in[1];
    const float* Wq    = (const float*)d_in[2];
    const float* gq    = (const float*)d_in[3];
    const float* bq    = (const float*)d_in[4];
    const float* Wk    = (const float*)d_in[5];
    const float* gk    = (const float*)d_in[6];
    const float* bk    = (const float*)d_in[7];
    const float* Wproj = (const float*)d_in[8];
    const float* rpb1  = (const float*)d_in[9];
    const float* rpb2  = (const float*)d_in[10];
    const float* Wdy   = (const float*)d_in[11];
    const float* bn_g  = (const float*)d_in[12];
    const float* bn_b  = (const float*)d_in[13];
    float* out = (float*)d_out;

    const int GSMEM   = 2 * GWORDS * 4;                   // 73728
    const int G1SMEM  = 2 * G1WORDS * 4;                  // 108544
    const int WGSMEM  = (128 * 68 + 80 * 68) * 4;         // 56576
    const int AVSMEM  = 14 * 14 * 68 * 4;                 // 53312
    cudaFuncSetAttribute(av_all_kernel, cudaFuncAttributeMaxDynamicSharedMemorySize, AVSMEM);
    cudaFuncSetAttribute(gemm1_ln_kernel, cudaFuncAttributeMaxDynamicSharedMemorySize, G1SMEM);
    cudaFuncSetAttribute(wgt_mma_kernel, cudaFuncAttributeMaxDynamicSharedMemorySize, WGSMEM);
    cudaFuncSetAttribute(mma_gemm_kernel<0>, cudaFuncAttributeMaxDynamicSharedMemorySize, GSMEM);
    cudaFuncSetAttribute(mma_gemm_kernel<1>, cudaFuncAttributeMaxDynamicSharedMemorySize, GSMEM);

    static float *p_kctx = nullptr, *p_kraw = nullptr, *p_mid = nullptr,
                 *p_wqtf = nullptr, *p_wktf = nullptr, *p_wdytf = nullptr;
    if (!p_kctx) {
        cudaGetSymbolAddress((void**)&p_kctx,  g_kctx);
        cudaGetSymbolAddress((void**)&p_kraw,  g_kraw);
        cudaGetSymbolAddress((void**)&p_mid,   g_mid);
        cudaGetSymbolAddress((void**)&p_wqtf,  g_wqtf);
        cudaGetSymbolAddress((void**)&p_wktf,  g_wktf);
        cudaGetSymbolAddress((void**)&p_wdytf, g_wdytf);
    }

    wconv_kernel<<<DIMC*DIMC/256, 256>>>(Wq, Wk, Wdy);
    pool_kernel<<<dim3(49, NB), 256>>>(ctx);
    mma_gemm_kernel<0><<<dim3(2, 2, 1), 256, GSMEM>>>(p_kctx, p_wktf, p_kraw, nullptr, nullptr, NB*49, 0);
    kfp_kernel<<<dim3(NB*NHEAD, 5), 256>>>(Wproj, gk, bk);
    gemm1_ln_kernel<<<dim3(32, 1, NB), 512, G1SMEM>>>(x, p_wqtf, gq, bq);
    wgt_mma_kernel<<<dim3(32, 16), 256, WGSMEM>>>(rpb1, rpb2);
    av_all_kernel<<<dim3(64, 4, NB), 256, AVSMEM>>>(x);
    mma_gemm_kernel<1><<<dim3(32, 2, NB), 256, GSMEM>>>(p_mid, p_wdytf, out, bn_g, bn_b, NPOS, NPOS*DIMC);
}

// round 16
// speedup vs baseline: 1.1211x; 1.1211x over previous
#include <cuda_runtime.h>
#include <cstdint>
#include <math.h>

#define NB 4
#define DIMC 256
#define HH 64
#define WW 64
#define NPOS (HH*WW)
#define NHEAD 4
#define HD 64

// ---------------- scratch ----------------
__device__ float g_qt[NB*NPOS*DIMC];         // LN(q)*scale, tf32-rounded [b][n][o]
__device__ float g_kctx[NB*49*DIMC];         // pooled ctx, tf32-rounded
__device__ float g_kraw[256*DIMC];           // Wk@kctx raw fp32 (196 rows used)
__device__ float2 g_kpart[2][256];           // per-n-half row partials (sum, sum2)
__device__ float g_kfp[NB*NHEAD*80*64];      // folded proj, tf32-rounded [bg][m pad80][c]
__device__ float g_attn[NB*NHEAD*NPOS*52];   // softmaxed attn
__device__ float g_mid[NB*NPOS*DIMC];        // AV out, tf32-rounded [b][n][c]
__device__ float g_wqtf[DIMC*DIMC];          // tf32-rounded weights
__device__ float g_wktf[DIMC*DIMC];
__device__ float g_wdytf[DIMC*DIMC];

__device__ __forceinline__ void cvt_tf32(uint32_t& r) {
    asm("cvt.rna.tf32.f32 %0, %0;" : "+r"(r));
}
__device__ __forceinline__ float rnd_tf32(float f) {
    uint32_t r; asm("cvt.rna.tf32.f32 %0, %1;" : "=r"(r) : "f"(f));
    return __uint_as_float(r);
}
__device__ __forceinline__ void cp16(uint32_t saddr, const void* gaddr) {
    asm volatile("cp.async.ca.shared.global [%0], [%1], 16;" :: "r"(saddr), "l"(gaddr));
}
#define CP_COMMIT() asm volatile("cp.async.commit_group;" ::: "memory")
#define CP_WAIT1()  asm volatile("cp.async.wait_group 1;" ::: "memory")
#define CP_WAIT0()  asm volatile("cp.async.wait_group 0;" ::: "memory")

// ---------------- weight pre-convert ----------------
__global__ __launch_bounds__(256) void wconv_kernel(const float* __restrict__ Wq,
                                                    const float* __restrict__ Wk,
                                                    const float* __restrict__ Wdy) {
    int idx = blockIdx.x * 256 + threadIdx.x;
    g_wqtf[idx]  = rnd_tf32(Wq[idx]);
    g_wktf[idx]  = rnd_tf32(Wk[idx]);
    g_wdytf[idx] = rnd_tf32(Wdy[idx]);
}

// ================= gemm1 + fused LN (cp.async double-buffered) =================
#define ASTR 136
#define G1WORDS (32*ASTR + 256*36)     // words per buffer
__global__ __launch_bounds__(512, 1)
void gemm1_ln_kernel(const float* __restrict__ x, const float* __restrict__ Wq,
                     const float* __restrict__ gq, const float* __restrict__ bq) {
    extern __shared__ uint32_t sm[];                 // 2 x (As2[32*ASTR] ++ Bs[256*36])
    __shared__ float red_s[128][9];
    __shared__ float red_s2[128][9];
    __shared__ float sg[256], sb[256];

    int tid  = threadIdx.x;
    int wid  = tid >> 5, lane = tid & 31;
    int q    = lane >> 2, tq = lane & 3;
    int wm   = wid >> 3, wn = wid & 7;               // 2 x 8
    int z    = blockIdx.z;
    int m0   = blockIdx.x * 128;
    const float* xb = x + (size_t)z * DIMC * NPOS;
    uint32_t sbase = (uint32_t)__cvta_generic_to_shared(sm);

    if (tid < 256) { sg[tid] = gq[tid]; sb[tid] = bq[tid]; }

    float c[4][4][4];
#pragma unroll
    for (int mt = 0; mt < 4; mt++)
#pragma unroll
        for (int nt = 0; nt < 4; nt++)
#pragma unroll
            for (int i = 0; i < 4; i++) c[mt][nt][i] = 0.f;

    auto issue = [&](int ck, int s) {
        uint32_t abase = sbase + (uint32_t)(s * G1WORDS) * 4u;
        uint32_t bbase = abase + 32u * ASTR * 4u;
#pragma unroll
        for (int it = 0; it < 2; it++) {
            int slot = tid + it * 512;
            int cc = slot >> 5, n4 = slot & 31;
            cp16(abase + (uint32_t)(cc * ASTR + n4 * 4) * 4u,
                 xb + (size_t)(ck * 32 + cc) * NPOS + m0 + n4 * 4);
        }
#pragma unroll
        for (int it = 0; it < 4; it++) {
            int slot = tid + it * 512;
            int row = slot >> 3, c4 = slot & 7;
            cp16(bbase + (uint32_t)(row * 36 + c4 * 4) * 4u,
                 Wq + (size_t)row * DIMC + ck * 32 + c4 * 4);
        }
        CP_COMMIT();
    };

    issue(0, 0);
    for (int ck = 0; ck < 8; ck++) {
        int s = ck & 1;
        if (ck < 7) { issue(ck + 1, s ^ 1); CP_WAIT1(); }
        else        { CP_WAIT0(); }
        __syncthreads();
        const uint32_t* As2 = sm + s * G1WORDS;
        const uint32_t* Bs  = As2 + 32 * ASTR;
#pragma unroll
        for (int ks = 0; ks < 4; ks++) {
            int k0 = ks * 8;
            uint32_t a[4][4];
#pragma unroll
            for (int mt = 0; mt < 4; mt++) {
                int r = wm * 64 + mt * 16 + q;
                a[mt][0] = As2[(k0 + tq) * ASTR + r];
                a[mt][1] = As2[(k0 + tq) * ASTR + r + 8];
                a[mt][2] = As2[(k0 + tq + 4) * ASTR + r];
                a[mt][3] = As2[(k0 + tq + 4) * ASTR + r + 8];
                cvt_tf32(a[mt][0]); cvt_tf32(a[mt][1]); cvt_tf32(a[mt][2]); cvt_tf32(a[mt][3]);
            }
            uint32_t b[4][2];
#pragma unroll
            for (int nt = 0; nt < 4; nt++) {
                int o = wn * 32 + nt * 8 + q;
                b[nt][0] = Bs[o * 36 + k0 + tq];
                b[nt][1] = Bs[o * 36 + k0 + tq + 4];
            }
#pragma unroll
            for (int mt = 0; mt < 4; mt++)
#pragma unroll
                for (int nt = 0; nt < 4; nt++) {
                    asm volatile(
                        "mma.sync.aligned.m16n8k8.row.col.f32.tf32.tf32.f32 "
                        "{%0,%1,%2,%3}, {%4,%5,%6,%7}, {%8,%9}, {%0,%1,%2,%3};"
                        : "+f"(c[mt][nt][0]), "+f"(c[mt][nt][1]),
                          "+f"(c[mt][nt][2]), "+f"(c[mt][nt][3])
                        : "r"(a[mt][0]), "r"(a[mt][1]), "r"(a[mt][2]), "r"(a[mt][3]),
                          "r"(b[nt][0]), "r"(b[nt][1]));
                }
        }
        __syncthreads();
    }

    // ---- fused LN epilogue ----
#pragma unroll
    for (int mt = 0; mt < 4; mt++) {
#pragma unroll
        for (int h = 0; h < 2; h++) {
            float s = 0.f, s2 = 0.f;
#pragma unroll
            for (int nt = 0; nt < 4; nt++) {
                float v0 = c[mt][nt][2*h], v1 = c[mt][nt][2*h+1];
                s += v0 + v1; s2 += v0*v0 + v1*v1;
            }
            s  += __shfl_xor_sync(0xffffffffu, s, 1);
            s2 += __shfl_xor_sync(0xffffffffu, s2, 1);
            s  += __shfl_xor_sync(0xffffffffu, s, 2);
            s2 += __shfl_xor_sync(0xffffffffu, s2, 2);
            if (tq == 0) {
                int rl = wm * 64 + mt * 16 + q + h * 8;
                red_s[rl][wn] = s;
                red_s2[rl][wn] = s2;
            }
        }
    }
    __syncthreads();
    float* outb = g_qt + (size_t)z * NPOS * DIMC;
#pragma unroll
    for (int mt = 0; mt < 4; mt++) {
#pragma unroll
        for (int h = 0; h < 2; h++) {
            int rl = wm * 64 + mt * 16 + q + h * 8;
            float S = 0.f, S2 = 0.f;
#pragma unroll
            for (int w = 0; w < 8; w++) { S += red_s[rl][w]; S2 += red_s2[rl][w]; }
            float mu = S * (1.f/256.f);
            float var = S2 * (1.f/256.f) - mu * mu;
            float rs = rsqrtf(var + 1e-6f);
            float* rowp = outb + (size_t)(m0 + rl) * DIMC;
#pragma unroll
            for (int nt = 0; nt < 4; nt++) {
                int o = wn * 32 + nt * 8 + 2 * tq;
                float2 v;
                v.x = rnd_tf32(((c[mt][nt][2*h]   - mu) * rs * sg[o]   + sb[o])   * 0.125f);
                v.y = rnd_tf32(((c[mt][nt][2*h+1] - mu) * rs * sg[o+1] + sb[o+1]) * 0.125f);
                *(float2*)(rowp + o) = v;
            }
        }
    }
}

// ================= generic mma.sync tf32 GEMM (cp.async, cvt-free) =================
#define GWORDS (2 * 128 * 36)
template<int EPI>
__global__ __launch_bounds__(256, 2)
void mma_gemm_kernel(const float* __restrict__ A, const float* __restrict__ B,
                     float* __restrict__ Out, const float* __restrict__ p1,
                     const float* __restrict__ p2, int mvalid, int batchStride) {
    extern __shared__ uint32_t sm[];
    __shared__ float sp1[256], sp2[256];
    __shared__ float prs[128][4], prs2[128][4];    // EPI 0 stat partials

    int tid = threadIdx.x;
    int wid = tid >> 5;
    int lane = tid & 31;
    int q = lane >> 2, tq = lane & 3;
    int wm = wid >> 2, wn = wid & 3;
    int z = blockIdx.z;
    int m0 = blockIdx.x * 128;
    int n0 = blockIdx.y * 128;
    const float* Ab = A + (size_t)z * batchStride;
    uint32_t sbase = (uint32_t)__cvta_generic_to_shared(sm);

    if (EPI == 1) { sp1[tid] = p1[tid] * rsqrtf(1.f + 1e-5f); sp2[tid] = p2[tid]; }

    float c[4][4][4];
#pragma unroll
    for (int mt = 0; mt < 4; mt++)
#pragma unroll
        for (int nt = 0; nt < 4; nt++)
#pragma unroll
            for (int i = 0; i < 4; i++) c[mt][nt][i] = 0.f;

    auto issue = [&](int ck, int s) {
        uint32_t abase = sbase + (uint32_t)(s * GWORDS) * 4u;
        uint32_t bbase = abase + 128u * 36u * 4u;
#pragma unroll
        for (int t = 0; t < 4; t++) {
            int idx = tid + t * 256;
            int row = idx >> 3, c4 = idx & 7;
            int ga = min(m0 + row, mvalid - 1);
            cp16(abase + (uint32_t)(row * 36 + c4 * 4) * 4u,
                 Ab + (size_t)ga * DIMC + ck * 32 + c4 * 4);
            cp16(bbase + (uint32_t)(row * 36 + c4 * 4) * 4u,
                 B + (size_t)(n0 + row) * DIMC + ck * 32 + c4 * 4);
        }
        CP_COMMIT();
    };

    issue(0, 0);
    for (int ck = 0; ck < 8; ck++) {
        int s = ck & 1;
        if (ck < 7) { issue(ck + 1, s ^ 1); CP_WAIT1(); }
        else        { CP_WAIT0(); }
        __syncthreads();
        const uint32_t* As = sm + s * GWORDS;
        const uint32_t* Bs = As + 128 * 36;
#pragma unroll
        for (int ks = 0; ks < 4; ks++) {
            int k0 = ks * 8;
            uint32_t a[4][4];
#pragma unroll
            for (int mt = 0; mt < 4; mt++) {
                int r = wm * 64 + mt * 16 + q;
                a[mt][0] = As[r * 36 + k0 + tq];
                a[mt][1] = As[(r + 8) * 36 + k0 + tq];
                a[mt][2] = As[r * 36 + k0 + tq + 4];
                a[mt][3] = As[(r + 8) * 36 + k0 + tq + 4];
            }
            uint32_t b[4][2];
#pragma unroll
            for (int nt = 0; nt < 4; nt++) {
                int nn = wn * 32 + nt * 8 + q;
                b[nt][0] = Bs[nn * 36 + k0 + tq];
                b[nt][1] = Bs[nn * 36 + k0 + tq + 4];
            }
#pragma unroll
            for (int mt = 0; mt < 4; mt++)
#pragma unroll
                for (int nt = 0; nt < 4; nt++) {
                    asm volatile(
                        "mma.sync.aligned.m16n8k8.row.col.f32.tf32.tf32.f32 "
                        "{%0,%1,%2,%3}, {%4,%5,%6,%7}, {%8,%9}, {%0,%1,%2,%3};"
                        : "+f"(c[mt][nt][0]), "+f"(c[mt][nt][1]),
                          "+f"(c[mt][nt][2]), "+f"(c[mt][nt][3])
                        : "r"(a[mt][0]), "r"(a[mt][1]), "r"(a[mt][2]), "r"(a[mt][3]),
                          "r"(b[nt][0]), "r"(b[nt][1]));
                }
        }
        __syncthreads();
    }

#pragma unroll
    for (int mt = 0; mt < 4; mt++) {
        int r0 = m0 + wm * 64 + mt * 16 + q;
#pragma unroll
        for (int nt = 0; nt < 4; nt++) {
            int o0 = n0 + wn * 32 + nt * 8 + 2 * tq;
            if (EPI == 0) {
                if (r0 < mvalid) {
                    float2 v = make_float2(c[mt][nt][0], c[mt][nt][1]);
                    *(float2*)(Out + (size_t)(z * NPOS + r0) * DIMC + o0) = v;
                }
                if (r0 + 8 < mvalid) {
                    float2 v = make_float2(c[mt][nt][2], c[mt][nt][3]);
                    *(float2*)(Out + (size_t)(z * NPOS + r0 + 8) * DIMC + o0) = v;
                }
            } else {
                float s0 = sp1[o0],     h0 = sp2[o0];
                float s1 = sp1[o0 + 1], h1 = sp2[o0 + 1];
                float* base0 = Out + ((size_t)(z * DIMC + o0)) * NPOS;
                float* base1 = Out + ((size_t)(z * DIMC + o0 + 1)) * NPOS;
                base0[r0]     = c[mt][nt][0] * s0 + h0;
                base1[r0]     = c[mt][nt][1] * s1 + h1;
                base0[r0 + 8] = c[mt][nt][2] * s0 + h0;
                base1[r0 + 8] = c[mt][nt][3] * s1 + h1;
            }
        }
    }

    if (EPI == 0) {
#pragma unroll
        for (int mt = 0; mt < 4; mt++) {
#pragma unroll
            for (int h = 0; h < 2; h++) {
                float s = 0.f, s2 = 0.f;
#pragma unroll
                for (int nt = 0; nt < 4; nt++) {
                    float v0 = c[mt][nt][2*h], v1 = c[mt][nt][2*h+1];
                    s += v0 + v1; s2 += v0*v0 + v1*v1;
                }
                s  += __shfl_xor_sync(0xffffffffu, s, 1);
                s2 += __shfl_xor_sync(0xffffffffu, s2, 1);
                s  += __shfl_xor_sync(0xffffffffu, s, 2);
                s2 += __shfl_xor_sync(0xffffffffu, s2, 2);
                if (tq == 0) {
                    int rl = wm * 64 + mt * 16 + q + h * 8;
                    prs[rl][wn]  = s;
                    prs2[rl][wn] = s2;
                }
            }
        }
        __syncthreads();
        if (tid < 128) {
            float S  = prs[tid][0]  + prs[tid][1]  + prs[tid][2]  + prs[tid][3];
            float S2 = prs2[tid][0] + prs2[tid][1] + prs2[tid][2] + prs2[tid][3];
            g_kpart[blockIdx.y][m0 + tid] = make_float2(S, S2);
        }
    }
}

// ---------------- ctx 8x8 avg pool (warp-per-channel, tf32-rounded out) ----------------
__global__ __launch_bounds__(256) void pool_kernel(const float* __restrict__ ctx) {
    int l = blockIdx.x, b = blockIdx.y;
    int li = l / 7, lj = l % 7;
    int wid = threadIdx.x >> 5, lane = threadIdx.x & 31;
    int ri = lane >> 2, rj = lane & 3;
    const float* base = ctx + (size_t)b * DIMC * 3136 + (li * 8 + ri) * 56 + lj * 8 + rj * 2;
    float* outp = g_kctx + (size_t)(b * 49 + l) * DIMC;
#pragma unroll
    for (int k = 0; k < 32; k++) {
        int c = wid * 32 + k;
        float2 v = *(const float2*)(base + (size_t)c * 3136);
        float s = v.x + v.y;
#pragma unroll
        for (int o = 16; o >= 1; o >>= 1) s += __shfl_xor_sync(0xffffffffu, s, o);
        if (lane == 0) outp[c] = rnd_tf32(s * (1.f / 64.f));
    }
}

// ---------------- fold Wproj -> kfp[bg][m][c], grid (16 bg, 5 mg); stats precomputed ----------------
__global__ __launch_bounds__(256) void kfp_kernel(const float* __restrict__ Wproj,
                                                  const float* __restrict__ gk,
                                                  const float* __restrict__ bk) {
    __shared__ float smu[49], srs[49];
    __shared__ float sn[49 * 64];
    __shared__ float swp[16 * 49];
    int bg = blockIdx.x;
    int mg = blockIdx.y;
    int b = bg >> 2, gg = bg & 3;
    int tid = threadIdx.x;

    if (tid < 49) {
        int row = b * 49 + tid;
        float2 p0 = g_kpart[0][row];
        float2 p1 = g_kpart[1][row];
        float S  = p0.x + p1.x;
        float S2 = p0.y + p1.y;
        float mu = S * (1.f / DIMC);
        float var = S2 * (1.f / DIMC) - mu * mu;
        smu[tid] = mu;
        srs[tid] = rsqrtf(var + 1e-6f);
    }
    for (int idx = tid; idx < 16 * 49; idx += 256) {
        int m = mg * 16 + idx / 49;
        swp[idx] = (m < 74) ? Wproj[m * 49 + (idx % 49)] : 0.f;
    }
    __syncthreads();
    for (int idx = tid; idx < 49 * 64; idx += 256) {
        int l = idx >> 6, c = idx & 63;
        sn[idx] = (g_kraw[(size_t)(b * 49 + l) * DIMC + gg * HD + c] - smu[l]) * srs[l];
    }
    __syncthreads();

    int c = tid & 63, mb = tid >> 6;
    float gkv = gk[gg * HD + c], bkv = bk[gg * HD + c];
    float* outp = g_kfp + (size_t)bg * 80 * 64;
    float acc[4] = {0.f, 0.f, 0.f, 0.f};
    float sw[4]  = {0.f, 0.f, 0.f, 0.f};
    for (int l = 0; l < 49; l++) {
        float v = sn[l * 64 + c];
#pragma unroll
        for (int mm = 0; mm < 4; mm++) {
            float w = swp[(mb * 4 + mm) * 49 + l];
            acc[mm] += v * w;
            sw[mm]  += w;
        }
    }
#pragma unroll
    for (int mm = 0; mm < 4; mm++) {
        int m = mg * 16 + mb * 4 + mm;
        outp[m * 64 + c] = (m < 74) ? rnd_tf32(acc[mm] * gkv + sw[mm] * bkv) : 0.f;
    }
}

// ---------------- wgt mma GEMM [128 x 80 x 64] + RPB + softmax (cvt-free) ----------------
__global__ __launch_bounds__(256)
void wgt_mma_kernel(const float* __restrict__ rpb1, const float* __restrict__ rpb2) {
    extern __shared__ char smc[];
    uint32_t* As = (uint32_t*)smc;                 // [128][68]
    uint32_t* Bs = As + 128 * 68;                  // [80][68]
    float*    Wg = (float*)smc;                    // [128][85]
    __shared__ float srpb[169];

    int tid = threadIdx.x;
    int wid = tid >> 5, lane = tid & 31;
    int q = lane >> 2, tq = lane & 3;
    int wm = wid >> 1, wn = wid & 1;
    int m0 = blockIdx.x * 128;
    int gy = blockIdx.y;
    int b  = gy >> 2, g = gy & 3;

    if (g < 2) { if (tid < 81) srpb[tid] = rpb1[g*81 + tid]; }
    else       { if (tid < 169) srpb[tid] = rpb2[(g-2)*169 + tid]; }

    const float* Abase = g_qt + ((size_t)(b * NPOS + m0)) * DIMC + g * HD;
#pragma unroll
    for (int it = 0; it < 8; it++) {
        int slot = tid + it * 256;
        int row = slot >> 4, c4 = slot & 15;
        uint4 u = *(const uint4*)(Abase + (size_t)row * DIMC + c4 * 4);
        *(uint4*)(As + row * 68 + c4 * 4) = u;
    }
    const float* Bbase = g_kfp + (size_t)gy * 80 * 64;
#pragma unroll
    for (int it = 0; it < 5; it++) {
        int slot = tid + it * 256;
        int mrow = slot >> 4, c4 = slot & 15;
        uint4 u = *(const uint4*)(Bbase + (size_t)mrow * 64 + c4 * 4);
        *(uint4*)(Bs + mrow * 68 + c4 * 4) = u;
    }
    __syncthreads();

    float c[2][5][4];
#pragma unroll
    for (int mt = 0; mt < 2; mt++)
#pragma unroll
        for (int nt = 0; nt < 5; nt++)
#pragma unroll
            for (int i = 0; i < 4; i++) c[mt][nt][i] = 0.f;

#pragma unroll
    for (int ks = 0; ks < 8; ks++) {
        int k0 = ks * 8;
        uint32_t a[2][4];
#pragma unroll
        for (int mt = 0; mt < 2; mt++) {
            int r = wm * 32 + mt * 16 + q;
            a[mt][0] = As[r * 68 + k0 + tq];
            a[mt][1] = As[(r + 8) * 68 + k0 + tq];
            a[mt][2] = As[r * 68 + k0 + tq + 4];
            a[mt][3] = As[(r + 8) * 68 + k0 + tq + 4];
        }
        uint32_t bfr[5][2];
#pragma unroll
        for (int nt = 0; nt < 5; nt++) {
            int col = wn * 40 + nt * 8 + q;
            bfr[nt][0] = Bs[col * 68 + k0 + tq];
            bfr[nt][1] = Bs[col * 68 + k0 + tq + 4];
        }
#pragma unroll
        for (int mt = 0; mt < 2; mt++)
#pragma unroll
            for (int nt = 0; nt < 5; nt++) {
                asm volatile(
                    "mma.sync.aligned.m16n8k8.row.col.f32.tf32.tf32.f32 "
                    "{%0,%1,%2,%3}, {%4,%5,%6,%7}, {%8,%9}, {%0,%1,%2,%3};"
                    : "+f"(c[mt][nt][0]), "+f"(c[mt][nt][1]),
                      "+f"(c[mt][nt][2]), "+f"(c[mt][nt][3])
                    : "r"(a[mt][0]), "r"(a[mt][1]), "r"(a[mt][2]), "r"(a[mt][3]),
                      "r"(bfr[nt][0]), "r"(bfr[nt][1]));
            }
    }
    __syncthreads();

#pragma unroll
    for (int mt = 0; mt < 2; mt++) {
        int r = wm * 32 + mt * 16 + q;
#pragma unroll
        for (int nt = 0; nt < 5; nt++) {
            int col = wn * 40 + nt * 8 + 2 * tq;
            Wg[r * 85 + col]       = c[mt][nt][0];
            Wg[r * 85 + col + 1]   = c[mt][nt][1];
            Wg[(r+8) * 85 + col]   = c[mt][nt][2];
            Wg[(r+8) * 85 + col+1] = c[mt][nt][3];
        }
    }
    __syncthreads();

    if (tid < 128) {
        int n = m0 + tid;
        int i = n >> 6, j = n & 63;
        float* wrow = Wg + tid * 85;
        float* arow = g_attn + ((size_t)(gy * NPOS + n)) * 52;
        if (g < 2) {
            int si = min(max(i-2,0),HH-5), sj = min(max(j-2,0),WW-5);
            int bi = 4 - (i - si), bj = 4 - (j - sj);
            float mx = -1e30f;
#pragma unroll
            for (int m = 0; m < 25; m++) {
                int p = m / 5, qq = m - p*5;
                float v = wrow[m] + srpb[(bi+p)*9 + bj + qq];
                wrow[m] = v;
                mx = fmaxf(mx, v);
            }
            float sum = 0.f;
#pragma unroll
            for (int m = 0; m < 25; m++) {
                float e = __expf(wrow[m] - mx);
                wrow[m] = e; sum += e;
            }
            float inv = 1.f / sum;
#pragma unroll
            for (int m = 0; m < 25; m++) arow[m] = wrow[m] * inv;
        } else {
            int si = min(max(i-3,0),HH-7), sj = min(max(j-3,0),WW-7);
            int bi = 6 - (i - si), bj = 6 - (j - sj);
            float mx = -1e30f;
#pragma unroll
            for (int t = 0; t < 49; t++) {
                int p = t / 7, qq = t - p*7;
                float v = wrow[25 + t] + srpb[(bi+p)*13 + bj + qq];
                wrow[25 + t] = v;
                mx = fmaxf(mx, v);
            }
            float sum = 0.f;
#pragma unroll
            for (int t = 0; t < 49; t++) {
                float e = __expf(wrow[25 + t] - mx);
                wrow[25 + t] = e; sum += e;
            }
            float inv = 1.f / sum;
#pragma unroll
            for (int t = 0; t < 49; t++) arow[t] = wrow[25 + t] * inv;
        }
    }
}

// ---------------- neighborhood AV (pixel-paired, tf32-rounded out) ----------------
template<int KK>
__device__ __forceinline__ void av_body(const float* __restrict__ x, int g, float* vs) {
    const int HALO = 8 + KK - 1;
    int ti0 = (blockIdx.x >> 3) * 8, tj0 = (blockIdx.x & 7) * 8;
    int b = blockIdx.z;
    int hbi = min(max(ti0 - KK/2, 0), HH - HALO);
    int hbj = min(max(tj0 - KK/2, 0), WW - HALO);
    const float* xb = x + (size_t)(b*DIMC + g*HD)*NPOS;
    for (int idx = threadIdx.x; idx < HALO*HALO*HD; idx += 256) {
        int c  = idx / (HALO*HALO);
        int rr = idx - c*HALO*HALO;
        int ri = rr / HALO, rj = rr - ri*HALO;
        vs[rr*68 + c] = xb[(size_t)c*NPOS + (hbi+ri)*WW + hbj + rj];
    }
    __syncthreads();
    int t = threadIdx.x;
    int pairIdx = t >> 3, cg = t & 7;
    int i  = ti0 + (pairIdx >> 2);
    int j0 = tj0 + (pairIdx & 3) * 2;
    int si  = min(max(i  - KK/2, 0), HH-KK) - hbi;
    int sj0 = min(max(j0     - KK/2, 0), WW-KK) - hbj;
    int sj1 = min(max(j0 + 1 - KK/2, 0), WW-KK) - hbj;
    int off1 = sj1 - sj0;
    int n0 = i*WW + j0;
    const float* ar0 = g_attn + ((size_t)((b*NHEAD+g)*NPOS + n0))*52;
    const float* ar1 = ar0 + 52;
    float4 p0a = make_float4(0,0,0,0), p0b = p0a, p1a = p0a, p1b = p0a;
    int qend = KK + off1;
#pragma unroll
    for (int p = 0; p < KK; p++) {
        const float* aw0 = ar0 + p*KK;
        const float* aw1 = ar1 + p*KK - off1;
        const float* vrow = &vs[((si+p)*HALO + sj0)*68 + cg*8];
        for (int q = 0; q < qend; q++) {
            const float4* vp = reinterpret_cast<const float4*>(vrow + q*68);
            float4 v0 = vp[0], v1 = vp[1];
            float w0 = (q < KK) ? __ldg(aw0 + q) : 0.f;
            float w1 = (q >= off1) ? __ldg(aw1 + q) : 0.f;
            p0a.x += w0*v0.x; p0a.y += w0*v0.y; p0a.z += w0*v0.z; p0a.w += w0*v0.w;
            p0b.x += w0*v1.x; p0b.y += w0*v1.y; p0b.z += w0*v1.z; p0b.w += w0*v1.w;
            p1a.x += w1*v0.x; p1a.y += w1*v0.y; p1a.z += w1*v0.z; p1a.w += w1*v0.w;
            p1b.x += w1*v1.x; p1b.y += w1*v1.y; p1b.z += w1*v1.z; p1b.w += w1*v1.w;
        }
    }
    p0a.x = rnd_tf32(p0a.x); p0a.y = rnd_tf32(p0a.y); p0a.z = rnd_tf32(p0a.z); p0a.w = rnd_tf32(p0a.w);
    p0b.x = rnd_tf32(p0b.x); p0b.y = rnd_tf32(p0b.y); p0b.z = rnd_tf32(p0b.z); p0b.w = rnd_tf32(p0b.w);
    p1a.x = rnd_tf32(p1a.x); p1a.y = rnd_tf32(p1a.y); p1a.z = rnd_tf32(p1a.z); p1a.w = rnd_tf32(p1a.w);
    p1b.x = rnd_tf32(p1b.x); p1b.y = rnd_tf32(p1b.y); p1b.z = rnd_tf32(p1b.z); p1b.w = rnd_tf32(p1b.w);
    float* op0 = g_mid + ((size_t)(b*NPOS + n0))*DIMC + g*HD + cg*8;
    float* op1 = op0 + DIMC;
    ((float4*)op0)[0] = p0a; ((float4*)op0)[1] = p0b;
    ((float4*)op1)[0] = p1a; ((float4*)op1)[1] = p1b;
}

__global__ __launch_bounds__(256) void av_all_kernel(const float* __restrict__ x) {
    extern __shared__ float vs[];
    int g = blockIdx.y;
    if (g < 2) av_body<5>(x, g, vs);
    else       av_body<7>(x, g, vs);
}

extern "C" void kernel_launch(void* const* d_in, const int* in_sizes, int n_in,
                              void* d_out, int out_size) {
    const float* x     = (const float*)d_in[0];
    const float* ctx   = (const float*)d_in[1];
    const float* Wq    = (const float*)d_in[2];
    const float* gq    = (const float*)d_in[3];
    const float* bq    = (const float*)d_in[4];
    const float* Wk    = (const float*)d_in[5];
    const float* gk    = (const float*)d_in[6];
    const float* bk    = (const float*)d_in[7];
    const float* Wproj = (const float*)d_in[8];
    const float* rpb1  = (const float*)d_in[9];
    const float* rpb2  = (const float*)d_in[10];
    const float* Wdy   = (const float*)d_in[11];
    const float* bn_g  = (const float*)d_in[12];
    const float* bn_b  = (const float*)d_in[13];
    float* out = (float*)d_out;

    const int GSMEM   = 2 * GWORDS * 4;                   // 73728
    const int G1SMEM  = 2 * G1WORDS * 4;                  // 108544
    const int WGSMEM  = (128 * 68 + 80 * 68) * 4;         // 56576
    const int AVSMEM  = 14 * 14 * 68 * 4;                 // 53312
    cudaFuncSetAttribute(av_all_kernel, cudaFuncAttributeMaxDynamicSharedMemorySize, AVSMEM);
    cudaFuncSetAttribute(gemm1_ln_kernel, cudaFuncAttributeMaxDynamicSharedMemorySize, G1SMEM);
    cudaFuncSetAttribute(wgt_mma_kernel, cudaFuncAttributeMaxDynamicSharedMemorySize, WGSMEM);
    cudaFuncSetAttribute(mma_gemm_kernel<0>, cudaFuncAttributeMaxDynamicSharedMemorySize, GSMEM);
    cudaFuncSetAttribute(mma_gemm_kernel<1>, cudaFuncAttributeMaxDynamicSharedMemorySize, GSMEM);

    static float *p_kctx = nullptr, *p_kraw = nullptr, *p_mid = nullptr,
                 *p_wqtf = nullptr, *p_wktf = nullptr, *p_wdytf = nullptr;
    static cudaStream_t s1 = nullptr;
    static cudaEvent_t evFork = nullptr, evJoin = nullptr;
    if (!p_kctx) {
        cudaGetSymbolAddress((void**)&p_kctx,  g_kctx);
        cudaGetSymbolAddress((void**)&p_kraw,  g_kraw);
        cudaGetSymbolAddress((void**)&p_mid,   g_mid);
        cudaGetSymbolAddress((void**)&p_wqtf,  g_wqtf);
        cudaGetSymbolAddress((void**)&p_wktf,  g_wktf);
        cudaGetSymbolAddress((void**)&p_wdytf, g_wdytf);
        cudaStreamCreateWithFlags(&s1, cudaStreamNonBlocking);
        cudaEventCreateWithFlags(&evFork, cudaEventDisableTiming);
        cudaEventCreateWithFlags(&evJoin, cudaEventDisableTiming);
    }

    // main stream: weight convert, then fork the kf chain onto s1
    wconv_kernel<<<DIMC*DIMC/256, 256>>>(Wq, Wk, Wdy);
    cudaEventRecord(evFork, 0);
    cudaStreamWaitEvent(s1, evFork, 0);

    // side stream: pooled-context -> kf GEMM -> folded projection
    pool_kernel<<<dim3(49, NB), 256, 0, s1>>>(ctx);
    mma_gemm_kernel<0><<<dim3(2, 2, 1), 256, GSMEM, s1>>>(p_kctx, p_wktf, p_kraw, nullptr, nullptr, NB*49, 0);
    kfp_kernel<<<dim3(NB*NHEAD, 5), 256, 0, s1>>>(Wproj, gk, bk);
    cudaEventRecord(evJoin, s1);

    // main stream: gemm1 runs concurrently with the kf chain
    gemm1_ln_kernel<<<dim3(32, 1, NB), 512, G1SMEM>>>(x, p_wqtf, gq, bq);
    cudaStreamWaitEvent(0, evJoin, 0);

    wgt_mma_kernel<<<dim3(32, 16), 256, WGSMEM>>>(rpb1, rpb2);
    av_all_kernel<<<dim3(64, 4, NB), 256, AVSMEM>>>(x);
    mma_gemm_kernel<1><<<dim3(32, 2, NB), 256, GSMEM>>>(p_mid, p_wdytf, out, bn_g, bn_b, NPOS, NPOS*DIMC);
}

// round 17
// speedup vs baseline: 1.3235x; 1.1806x over previous
#include <cuda_runtime.h>
#include <cstdint>
#include <math.h>

#define NB 4
#define DIMC 256
#define HH 64
#define WW 64
#define NPOS (HH*WW)
#define NHEAD 4
#define HD 64

// ---------------- scratch ----------------
__device__ float g_qt[NB*NPOS*DIMC];         // LN(q)*scale, tf32-rounded [b][n][o]
__device__ float g_kctx[NB*49*DIMC];         // pooled ctx, tf32-rounded
__device__ float g_kraw[256*DIMC];           // Wk@kctx raw fp32 (196 rows used)
__device__ float2 g_kpart[2][256];           // per-n-half row partials (sum, sum2)
__device__ float g_kfp[NB*NHEAD*80*64];      // folded proj, tf32-rounded [bg][m pad80][c]
__device__ float g_mid[NB*NPOS*DIMC];        // AV out, tf32-rounded [b][n][c]
__device__ float g_wqtf[DIMC*DIMC];          // tf32-rounded weights
__device__ float g_wktf[DIMC*DIMC];
__device__ float g_wdytf[DIMC*DIMC];

__device__ __forceinline__ void cvt_tf32(uint32_t& r) {
    asm("cvt.rna.tf32.f32 %0, %0;" : "+r"(r));
}
__device__ __forceinline__ float rnd_tf32(float f) {
    uint32_t r; asm("cvt.rna.tf32.f32 %0, %1;" : "=r"(r) : "f"(f));
    return __uint_as_float(r);
}
__device__ __forceinline__ void cp16(uint32_t saddr, const void* gaddr) {
    asm volatile("cp.async.ca.shared.global [%0], [%1], 16;" :: "r"(saddr), "l"(gaddr));
}
#define CP_COMMIT() asm volatile("cp.async.commit_group;" ::: "memory")
#define CP_WAIT1()  asm volatile("cp.async.wait_group 1;" ::: "memory")
#define CP_WAIT0()  asm volatile("cp.async.wait_group 0;" ::: "memory")

// ---------------- weight pre-convert ----------------
__global__ __launch_bounds__(256) void wconv_kernel(const float* __restrict__ Wq,
                                                    const float* __restrict__ Wk,
                                                    const float* __restrict__ Wdy) {
    int idx = blockIdx.x * 256 + threadIdx.x;
    g_wqtf[idx]  = rnd_tf32(Wq[idx]);
    g_wktf[idx]  = rnd_tf32(Wk[idx]);
    g_wdytf[idx] = rnd_tf32(Wdy[idx]);
}

// ================= gemm1 + fused LN (cp.async double-buffered) =================
#define ASTR 136
#define G1WORDS (32*ASTR + 256*36)
__global__ __launch_bounds__(512, 1)
void gemm1_ln_kernel(const float* __restrict__ x, const float* __restrict__ Wq,
                     const float* __restrict__ gq, const float* __restrict__ bq) {
    extern __shared__ uint32_t sm[];
    __shared__ float red_s[128][9];
    __shared__ float red_s2[128][9];
    __shared__ float sg[256], sb[256];

    int tid  = threadIdx.x;
    int wid  = tid >> 5, lane = tid & 31;
    int q    = lane >> 2, tq = lane & 3;
    int wm   = wid >> 3, wn = wid & 7;
    int z    = blockIdx.z;
    int m0   = blockIdx.x * 128;
    const float* xb = x + (size_t)z * DIMC * NPOS;
    uint32_t sbase = (uint32_t)__cvta_generic_to_shared(sm);

    if (tid < 256) { sg[tid] = gq[tid]; sb[tid] = bq[tid]; }

    float c[4][4][4];
#pragma unroll
    for (int mt = 0; mt < 4; mt++)
#pragma unroll
        for (int nt = 0; nt < 4; nt++)
#pragma unroll
            for (int i = 0; i < 4; i++) c[mt][nt][i] = 0.f;

    auto issue = [&](int ck, int s) {
        uint32_t abase = sbase + (uint32_t)(s * G1WORDS) * 4u;
        uint32_t bbase = abase + 32u * ASTR * 4u;
#pragma unroll
        for (int it = 0; it < 2; it++) {
            int slot = tid + it * 512;
            int cc = slot >> 5, n4 = slot & 31;
            cp16(abase + (uint32_t)(cc * ASTR + n4 * 4) * 4u,
                 xb + (size_t)(ck * 32 + cc) * NPOS + m0 + n4 * 4);
        }
#pragma unroll
        for (int it = 0; it < 4; it++) {
            int slot = tid + it * 512;
            int row = slot >> 3, c4 = slot & 7;
            cp16(bbase + (uint32_t)(row * 36 + c4 * 4) * 4u,
                 Wq + (size_t)row * DIMC + ck * 32 + c4 * 4);
        }
        CP_COMMIT();
    };

    issue(0, 0);
    for (int ck = 0; ck < 8; ck++) {
        int s = ck & 1;
        if (ck < 7) { issue(ck + 1, s ^ 1); CP_WAIT1(); }
        else        { CP_WAIT0(); }
        __syncthreads();
        const uint32_t* As2 = sm + s * G1WORDS;
        const uint32_t* Bs  = As2 + 32 * ASTR;
#pragma unroll
        for (int ks = 0; ks < 4; ks++) {
            int k0 = ks * 8;
            uint32_t a[4][4];
#pragma unroll
            for (int mt = 0; mt < 4; mt++) {
                int r = wm * 64 + mt * 16 + q;
                a[mt][0] = As2[(k0 + tq) * ASTR + r];
                a[mt][1] = As2[(k0 + tq) * ASTR + r + 8];
                a[mt][2] = As2[(k0 + tq + 4) * ASTR + r];
                a[mt][3] = As2[(k0 + tq + 4) * ASTR + r + 8];
                cvt_tf32(a[mt][0]); cvt_tf32(a[mt][1]); cvt_tf32(a[mt][2]); cvt_tf32(a[mt][3]);
            }
            uint32_t b[4][2];
#pragma unroll
            for (int nt = 0; nt < 4; nt++) {
                int o = wn * 32 + nt * 8 + q;
                b[nt][0] = Bs[o * 36 + k0 + tq];
                b[nt][1] = Bs[o * 36 + k0 + tq + 4];
            }
#pragma unroll
            for (int mt = 0; mt < 4; mt++)
#pragma unroll
                for (int nt = 0; nt < 4; nt++) {
                    asm volatile(
                        "mma.sync.aligned.m16n8k8.row.col.f32.tf32.tf32.f32 "
                        "{%0,%1,%2,%3}, {%4,%5,%6,%7}, {%8,%9}, {%0,%1,%2,%3};"
                        : "+f"(c[mt][nt][0]), "+f"(c[mt][nt][1]),
                          "+f"(c[mt][nt][2]), "+f"(c[mt][nt][3])
                        : "r"(a[mt][0]), "r"(a[mt][1]), "r"(a[mt][2]), "r"(a[mt][3]),
                          "r"(b[nt][0]), "r"(b[nt][1]));
                }
        }
        __syncthreads();
    }

#pragma unroll
    for (int mt = 0; mt < 4; mt++) {
#pragma unroll
        for (int h = 0; h < 2; h++) {
            float s = 0.f, s2 = 0.f;
#pragma unroll
            for (int nt = 0; nt < 4; nt++) {
                float v0 = c[mt][nt][2*h], v1 = c[mt][nt][2*h+1];
                s += v0 + v1; s2 += v0*v0 + v1*v1;
            }
            s  += __shfl_xor_sync(0xffffffffu, s, 1);
            s2 += __shfl_xor_sync(0xffffffffu, s2, 1);
            s  += __shfl_xor_sync(0xffffffffu, s, 2);
            s2 += __shfl_xor_sync(0xffffffffu, s2, 2);
            if (tq == 0) {
                int rl = wm * 64 + mt * 16 + q + h * 8;
                red_s[rl][wn] = s;
                red_s2[rl][wn] = s2;
            }
        }
    }
    __syncthreads();
    float* outb = g_qt + (size_t)z * NPOS * DIMC;
#pragma unroll
    for (int mt = 0; mt < 4; mt++) {
#pragma unroll
        for (int h = 0; h < 2; h++) {
            int rl = wm * 64 + mt * 16 + q + h * 8;
            float S = 0.f, S2 = 0.f;
#pragma unroll
            for (int w = 0; w < 8; w++) { S += red_s[rl][w]; S2 += red_s2[rl][w]; }
            float mu = S * (1.f/256.f);
            float var = S2 * (1.f/256.f) - mu * mu;
            float rs = rsqrtf(var + 1e-6f);
            float* rowp = outb + (size_t)(m0 + rl) * DIMC;
#pragma unroll
            for (int nt = 0; nt < 4; nt++) {
                int o = wn * 32 + nt * 8 + 2 * tq;
                float2 v;
                v.x = rnd_tf32(((c[mt][nt][2*h]   - mu) * rs * sg[o]   + sb[o])   * 0.125f);
                v.y = rnd_tf32(((c[mt][nt][2*h+1] - mu) * rs * sg[o+1] + sb[o+1]) * 0.125f);
                *(float2*)(rowp + o) = v;
            }
        }
    }
}

// ================= generic mma.sync tf32 GEMM (cp.async, cvt-free) =================
#define GWORDS (2 * 128 * 36)
template<int EPI>
__global__ __launch_bounds__(256, 2)
void mma_gemm_kernel(const float* __restrict__ A, const float* __restrict__ B,
                     float* __restrict__ Out, const float* __restrict__ p1,
                     const float* __restrict__ p2, int mvalid, int batchStride) {
    extern __shared__ uint32_t sm[];
    __shared__ float sp1[256], sp2[256];
    __shared__ float prs[128][4], prs2[128][4];

    int tid = threadIdx.x;
    int wid = tid >> 5;
    int lane = tid & 31;
    int q = lane >> 2, tq = lane & 3;
    int wm = wid >> 2, wn = wid & 3;
    int z = blockIdx.z;
    int m0 = blockIdx.x * 128;
    int n0 = blockIdx.y * 128;
    const float* Ab = A + (size_t)z * batchStride;
    uint32_t sbase = (uint32_t)__cvta_generic_to_shared(sm);

    if (EPI == 1) { sp1[tid] = p1[tid] * rsqrtf(1.f + 1e-5f); sp2[tid] = p2[tid]; }

    float c[4][4][4];
#pragma unroll
    for (int mt = 0; mt < 4; mt++)
#pragma unroll
        for (int nt = 0; nt < 4; nt++)
#pragma unroll
            for (int i = 0; i < 4; i++) c[mt][nt][i] = 0.f;

    auto issue = [&](int ck, int s) {
        uint32_t abase = sbase + (uint32_t)(s * GWORDS) * 4u;
        uint32_t bbase = abase + 128u * 36u * 4u;
#pragma unroll
        for (int t = 0; t < 4; t++) {
            int idx = tid + t * 256;
            int row = idx >> 3, c4 = idx & 7;
            int ga = min(m0 + row, mvalid - 1);
            cp16(abase + (uint32_t)(row * 36 + c4 * 4) * 4u,
                 Ab + (size_t)ga * DIMC + ck * 32 + c4 * 4);
            cp16(bbase + (uint32_t)(row * 36 + c4 * 4) * 4u,
                 B + (size_t)(n0 + row) * DIMC + ck * 32 + c4 * 4);
        }
        CP_COMMIT();
    };

    issue(0, 0);
    for (int ck = 0; ck < 8; ck++) {
        int s = ck & 1;
        if (ck < 7) { issue(ck + 1, s ^ 1); CP_WAIT1(); }
        else        { CP_WAIT0(); }
        __syncthreads();
        const uint32_t* As = sm + s * GWORDS;
        const uint32_t* Bs = As + 128 * 36;
#pragma unroll
        for (int ks = 0; ks < 4; ks++) {
            int k0 = ks * 8;
            uint32_t a[4][4];
#pragma unroll
            for (int mt = 0; mt < 4; mt++) {
                int r = wm * 64 + mt * 16 + q;
                a[mt][0] = As[r * 36 + k0 + tq];
                a[mt][1] = As[(r + 8) * 36 + k0 + tq];
                a[mt][2] = As[r * 36 + k0 + tq + 4];
                a[mt][3] = As[(r + 8) * 36 + k0 + tq + 4];
            }
            uint32_t b[4][2];
#pragma unroll
            for (int nt = 0; nt < 4; nt++) {
                int nn = wn * 32 + nt * 8 + q;
                b[nt][0] = Bs[nn * 36 + k0 + tq];
                b[nt][1] = Bs[nn * 36 + k0 + tq + 4];
            }
#pragma unroll
            for (int mt = 0; mt < 4; mt++)
#pragma unroll
                for (int nt = 0; nt < 4; nt++) {
                    asm volatile(
                        "mma.sync.aligned.m16n8k8.row.col.f32.tf32.tf32.f32 "
                        "{%0,%1,%2,%3}, {%4,%5,%6,%7}, {%8,%9}, {%0,%1,%2,%3};"
                        : "+f"(c[mt][nt][0]), "+f"(c[mt][nt][1]),
                          "+f"(c[mt][nt][2]), "+f"(c[mt][nt][3])
                        : "r"(a[mt][0]), "r"(a[mt][1]), "r"(a[mt][2]), "r"(a[mt][3]),
                          "r"(b[nt][0]), "r"(b[nt][1]));
                }
        }
        __syncthreads();
    }

#pragma unroll
    for (int mt = 0; mt < 4; mt++) {
        int r0 = m0 + wm * 64 + mt * 16 + q;
#pragma unroll
        for (int nt = 0; nt < 4; nt++) {
            int o0 = n0 + wn * 32 + nt * 8 + 2 * tq;
            if (EPI == 0) {
                if (r0 < mvalid) {
                    float2 v = make_float2(c[mt][nt][0], c[mt][nt][1]);
                    *(float2*)(Out + (size_t)(z * NPOS + r0) * DIMC + o0) = v;
                }
                if (r0 + 8 < mvalid) {
                    float2 v = make_float2(c[mt][nt][2], c[mt][nt][3]);
                    *(float2*)(Out + (size_t)(z * NPOS + r0 + 8) * DIMC + o0) = v;
                }
            } else {
                float s0 = sp1[o0],     h0 = sp2[o0];
                float s1 = sp1[o0 + 1], h1 = sp2[o0 + 1];
                float* base0 = Out + ((size_t)(z * DIMC + o0)) * NPOS;
                float* base1 = Out + ((size_t)(z * DIMC + o0 + 1)) * NPOS;
                base0[r0]     = c[mt][nt][0] * s0 + h0;
                base1[r0]     = c[mt][nt][1] * s1 + h1;
                base0[r0 + 8] = c[mt][nt][2] * s0 + h0;
                base1[r0 + 8] = c[mt][nt][3] * s1 + h1;
            }
        }
    }

    if (EPI == 0) {
#pragma unroll
        for (int mt = 0; mt < 4; mt++) {
#pragma unroll
            for (int h = 0; h < 2; h++) {
                float s = 0.f, s2 = 0.f;
#pragma unroll
                for (int nt = 0; nt < 4; nt++) {
                    float v0 = c[mt][nt][2*h], v1 = c[mt][nt][2*h+1];
                    s += v0 + v1; s2 += v0*v0 + v1*v1;
                }
                s  += __shfl_xor_sync(0xffffffffu, s, 1);
                s2 += __shfl_xor_sync(0xffffffffu, s2, 1);
                s  += __shfl_xor_sync(0xffffffffu, s, 2);
                s2 += __shfl_xor_sync(0xffffffffu, s2, 2);
                if (tq == 0) {
                    int rl = wm * 64 + mt * 16 + q + h * 8;
                    prs[rl][wn]  = s;
                    prs2[rl][wn] = s2;
                }
            }
        }
        __syncthreads();
        if (tid < 128) {
            float S  = prs[tid][0]  + prs[tid][1]  + prs[tid][2]  + prs[tid][3];
            float S2 = prs2[tid][0] + prs2[tid][1] + prs2[tid][2] + prs2[tid][3];
            g_kpart[blockIdx.y][m0 + tid] = make_float2(S, S2);
        }
    }
}

// ---------------- ctx 8x8 avg pool ----------------
__global__ __launch_bounds__(256) void pool_kernel(const float* __restrict__ ctx) {
    int l = blockIdx.x, b = blockIdx.y;
    int li = l / 7, lj = l % 7;
    int wid = threadIdx.x >> 5, lane = threadIdx.x & 31;
    int ri = lane >> 2, rj = lane & 3;
    const float* base = ctx + (size_t)b * DIMC * 3136 + (li * 8 + ri) * 56 + lj * 8 + rj * 2;
    float* outp = g_kctx + (size_t)(b * 49 + l) * DIMC;
#pragma unroll
    for (int k = 0; k < 32; k++) {
        int c = wid * 32 + k;
        float2 v = *(const float2*)(base + (size_t)c * 3136);
        float s = v.x + v.y;
#pragma unroll
        for (int o = 16; o >= 1; o >>= 1) s += __shfl_xor_sync(0xffffffffu, s, o);
        if (lane == 0) outp[c] = rnd_tf32(s * (1.f / 64.f));
    }
}

// ---------------- fold Wproj -> kfp ----------------
__global__ __launch_bounds__(256) void kfp_kernel(const float* __restrict__ Wproj,
                                                  const float* __restrict__ gk,
                                                  const float* __restrict__ bk) {
    __shared__ float smu[49], srs[49];
    __shared__ float sn[49 * 64];
    __shared__ float swp[16 * 49];
    int bg = blockIdx.x;
    int mg = blockIdx.y;
    int b = bg >> 2, gg = bg & 3;
    int tid = threadIdx.x;

    if (tid < 49) {
        int row = b * 49 + tid;
        float2 p0 = g_kpart[0][row];
        float2 p1 = g_kpart[1][row];
        float S  = p0.x + p1.x;
        float S2 = p0.y + p1.y;
        float mu = S * (1.f / DIMC);
        float var = S2 * (1.f / DIMC) - mu * mu;
        smu[tid] = mu;
        srs[tid] = rsqrtf(var + 1e-6f);
    }
    for (int idx = tid; idx < 16 * 49; idx += 256) {
        int m = mg * 16 + idx / 49;
        swp[idx] = (m < 74) ? Wproj[m * 49 + (idx % 49)] : 0.f;
    }
    __syncthreads();
    for (int idx = tid; idx < 49 * 64; idx += 256) {
        int l = idx >> 6, c = idx & 63;
        sn[idx] = (g_kraw[(size_t)(b * 49 + l) * DIMC + gg * HD + c] - smu[l]) * srs[l];
    }
    __syncthreads();

    int c = tid & 63, mb = tid >> 6;
    float gkv = gk[gg * HD + c], bkv = bk[gg * HD + c];
    float* outp = g_kfp + (size_t)bg * 80 * 64;
    float acc[4] = {0.f, 0.f, 0.f, 0.f};
    float sw[4]  = {0.f, 0.f, 0.f, 0.f};
    for (int l = 0; l < 49; l++) {
        float v = sn[l * 64 + c];
#pragma unroll
        for (int mm = 0; mm < 4; mm++) {
            float w = swp[(mb * 4 + mm) * 49 + l];
            acc[mm] += v * w;
            sw[mm]  += w;
        }
    }
#pragma unroll
    for (int mm = 0; mm < 4; mm++) {
        int m = mg * 16 + mb * 4 + mm;
        outp[m * 64 + c] = (m < 74) ? rnd_tf32(acc[mm] * gkv + sw[mm] * bkv) : 0.f;
    }
}

// ================= fused wgt(mma)+softmax+AV per 8x8 tile =================
#define WA_REGION 53312                          // aliased mma/Wg/halo bytes
#define WA_SMEM (WA_REGION + 64*52*4)            // + sattn = 66624

template<int KK>
__device__ __forceinline__ void halo_av(const float* __restrict__ x, float* vs,
                                        const float* sattn, int ti0, int tj0) {
    const int HALO = 8 + KK - 1;
    int g = blockIdx.y, b = blockIdx.z;
    int hbi = min(max(ti0 - KK/2, 0), HH - HALO);
    int hbj = min(max(tj0 - KK/2, 0), WW - HALO);
    const float* xb = x + (size_t)(b*DIMC + g*HD)*NPOS;
    for (int idx = threadIdx.x; idx < HALO*HALO*HD; idx += 256) {
        int c  = idx / (HALO*HALO);
        int rr = idx - c*HALO*HALO;
        int ri = rr / HALO, rj = rr - ri*HALO;
        vs[rr*68 + c] = xb[(size_t)c*NPOS + (hbi+ri)*WW + hbj + rj];
    }
    __syncthreads();
    int t = threadIdx.x;
    int pairIdx = t >> 3, cg = t & 7;
    int di = pairIdx >> 2, dj0 = (pairIdx & 3) * 2;
    int i  = ti0 + di;
    int j0 = tj0 + dj0;
    int si  = min(max(i  - KK/2, 0), HH-KK) - hbi;
    int sj0 = min(max(j0     - KK/2, 0), WW-KK) - hbj;
    int sj1 = min(max(j0 + 1 - KK/2, 0), WW-KK) - hbj;
    int off1 = sj1 - sj0;
    int n0 = i*WW + j0;
    const float* ar0 = sattn + (di*8 + dj0)*52;
    const float* ar1 = ar0 + 52;
    float4 p0a = make_float4(0,0,0,0), p0b = p0a, p1a = p0a, p1b = p0a;
    int qend = KK + off1;
#pragma unroll
    for (int p = 0; p < KK; p++) {
        const float* aw0 = ar0 + p*KK;
        const float* aw1 = ar1 + p*KK - off1;
        const float* vrow = &vs[((si+p)*HALO + sj0)*68 + cg*8];
        for (int q = 0; q < qend; q++) {
            const float4* vp = reinterpret_cast<const float4*>(vrow + q*68);
            float4 v0 = vp[0], v1 = vp[1];
            float w0 = (q < KK) ? aw0[q] : 0.f;
            float w1 = (q >= off1) ? aw1[q] : 0.f;
            p0a.x += w0*v0.x; p0a.y += w0*v0.y; p0a.z += w0*v0.z; p0a.w += w0*v0.w;
            p0b.x += w0*v1.x; p0b.y += w0*v1.y; p0b.z += w0*v1.z; p0b.w += w0*v1.w;
            p1a.x += w1*v0.x; p1a.y += w1*v0.y; p1a.z += w1*v0.z; p1a.w += w1*v0.w;
            p1b.x += w1*v1.x; p1b.y += w1*v1.y; p1b.z += w1*v1.z; p1b.w += w1*v1.w;
        }
    }
    p0a.x = rnd_tf32(p0a.x); p0a.y = rnd_tf32(p0a.y); p0a.z = rnd_tf32(p0a.z); p0a.w = rnd_tf32(p0a.w);
    p0b.x = rnd_tf32(p0b.x); p0b.y = rnd_tf32(p0b.y); p0b.z = rnd_tf32(p0b.z); p0b.w = rnd_tf32(p0b.w);
    p1a.x = rnd_tf32(p1a.x); p1a.y = rnd_tf32(p1a.y); p1a.z = rnd_tf32(p1a.z); p1a.w = rnd_tf32(p1a.w);
    p1b.x = rnd_tf32(p1b.x); p1b.y = rnd_tf32(p1b.y); p1b.z = rnd_tf32(p1b.z); p1b.w = rnd_tf32(p1b.w);
    float* op0 = g_mid + ((size_t)(b*NPOS + n0))*DIMC + g*HD + cg*8;
    float* op1 = op0 + DIMC;
    ((float4*)op0)[0] = p0a; ((float4*)op0)[1] = p0b;
    ((float4*)op1)[0] = p1a; ((float4*)op1)[1] = p1b;
}

__global__ __launch_bounds__(256)
void wgtav_kernel(const float* __restrict__ x,
                  const float* __restrict__ rpb1, const float* __restrict__ rpb2) {
    extern __shared__ char smc[];
    uint32_t* As = (uint32_t*)smc;               // [64][68]
    uint32_t* Bs = As + 64 * 68;                 // [80][68]
    float*    Wg = (float*)smc;                  // [64][85] (alias)
    float*    vs = (float*)smc;                  // halo (alias)
    float*    sattn = (float*)(smc + WA_REGION); // [64][52]
    __shared__ float srpb[169];

    int tid = threadIdx.x;
    int wid = tid >> 5, lane = tid & 31;
    int q = lane >> 2, tq = lane & 3;
    int wm = wid >> 1, wn = wid & 1;             // 4m x 2n
    int tile = blockIdx.x;
    int ti0 = (tile >> 3) * 8, tj0 = (tile & 7) * 8;
    int g = blockIdx.y, b = blockIdx.z;
    int gy = b * NHEAD + g;

    if (g < 2) { if (tid < 81) srpb[tid] = rpb1[g*81 + tid]; }
    else       { if (tid < 169) srpb[tid] = rpb2[(g-2)*169 + tid]; }

    // A: qt rows for the 64 tile pixels (row r -> pixel (ti0+r/8, tj0+r%8))
#pragma unroll
    for (int it = 0; it < 4; it++) {
        int slot = tid + it * 256;
        int row = slot >> 4, c4 = slot & 15;
        int n = (ti0 + (row >> 3)) * WW + tj0 + (row & 7);
        uint4 u = *(const uint4*)(g_qt + ((size_t)(b * NPOS + n)) * DIMC + g * HD + c4 * 4);
        *(uint4*)(As + row * 68 + c4 * 4) = u;
    }
    // B: kfp[gy][80][64]
#pragma unroll
    for (int it = 0; it < 5; it++) {
        int slot = tid + it * 256;
        int mrow = slot >> 4, c4 = slot & 15;
        uint4 u = *(const uint4*)(g_kfp + (size_t)gy * 80 * 64 + mrow * 64 + c4 * 4);
        *(uint4*)(Bs + mrow * 68 + c4 * 4) = u;
    }
    __syncthreads();

    float c[5][4];
#pragma unroll
    for (int nt = 0; nt < 5; nt++)
#pragma unroll
        for (int i = 0; i < 4; i++) c[nt][i] = 0.f;

#pragma unroll
    for (int ks = 0; ks < 8; ks++) {
        int k0 = ks * 8;
        int r = wm * 16 + q;
        uint32_t a0 = As[r * 68 + k0 + tq];
        uint32_t a1 = As[(r + 8) * 68 + k0 + tq];
        uint32_t a2 = As[r * 68 + k0 + tq + 4];
        uint32_t a3 = As[(r + 8) * 68 + k0 + tq + 4];
        uint32_t bfr[5][2];
#pragma unroll
        for (int nt = 0; nt < 5; nt++) {
            int col = wn * 40 + nt * 8 + q;
            bfr[nt][0] = Bs[col * 68 + k0 + tq];
            bfr[nt][1] = Bs[col * 68 + k0 + tq + 4];
        }
#pragma unroll
        for (int nt = 0; nt < 5; nt++) {
            asm volatile(
                "mma.sync.aligned.m16n8k8.row.col.f32.tf32.tf32.f32 "
                "{%0,%1,%2,%3}, {%4,%5,%6,%7}, {%8,%9}, {%0,%1,%2,%3};"
                : "+f"(c[nt][0]), "+f"(c[nt][1]), "+f"(c[nt][2]), "+f"(c[nt][3])
                : "r"(a0), "r"(a1), "r"(a2), "r"(a3),
                  "r"(bfr[nt][0]), "r"(bfr[nt][1]));
        }
    }
    __syncthreads();

    {
        int r = wm * 16 + q;
#pragma unroll
        for (int nt = 0; nt < 5; nt++) {
            int col = wn * 40 + nt * 8 + 2 * tq;
            Wg[r * 85 + col]       = c[nt][0];
            Wg[r * 85 + col + 1]   = c[nt][1];
            Wg[(r+8) * 85 + col]   = c[nt][2];
            Wg[(r+8) * 85 + col+1] = c[nt][3];
        }
    }
    __syncthreads();

    if (tid < 64) {
        int i = ti0 + (tid >> 3), j = tj0 + (tid & 7);
        float* wrow = Wg + tid * 85;
        float* arow = sattn + tid * 52;
        if (g < 2) {
            int si = min(max(i-2,0),HH-5), sj = min(max(j-2,0),WW-5);
            int bi = 4 - (i - si), bj = 4 - (j - sj);
            float mx = -1e30f;
#pragma unroll
            for (int m = 0; m < 25; m++) {
                int p = m / 5, qq = m - p*5;
                float v = wrow[m] + srpb[(bi+p)*9 + bj + qq];
                wrow[m] = v;
                mx = fmaxf(mx, v);
            }
            float sum = 0.f;
#pragma unroll
            for (int m = 0; m < 25; m++) {
                float e = __expf(wrow[m] - mx);
                wrow[m] = e; sum += e;
            }
            float inv = 1.f / sum;
#pragma unroll
            for (int m = 0; m < 25; m++) arow[m] = wrow[m] * inv;
        } else {
            int si = min(max(i-3,0),HH-7), sj = min(max(j-3,0),WW-7);
            int bi = 6 - (i - si), bj = 6 - (j - sj);
            float mx = -1e30f;
#pragma unroll
            for (int t = 0; t < 49; t++) {
                int p = t / 7, qq = t - p*7;
                float v = wrow[25 + t] + srpb[(bi+p)*13 + bj + qq];
                wrow[25 + t] = v;
                mx = fmaxf(mx, v);
            }
            float sum = 0.f;
#pragma unroll
            for (int t = 0; t < 49; t++) {
                float e = __expf(wrow[25 + t] - mx);
                wrow[25 + t] = e; sum += e;
            }
            float inv = 1.f / sum;
#pragma unroll
            for (int t = 0; t < 49; t++) arow[t] = wrow[25 + t] * inv;
        }
    }
    __syncthreads();   // sattn ready; Wg/As/Bs free for halo

    if (g < 2) halo_av<5>(x, vs, sattn, ti0, tj0);
    else       halo_av<7>(x, vs, sattn, ti0, tj0);
}

extern "C" void kernel_launch(void* const* d_in, const int* in_sizes, int n_in,
                              void* d_out, int out_size) {
    const float* x     = (const float*)d_in[0];
    const float* ctx   = (const float*)d_in[1];
    const float* Wq    = (const float*)d_in[2];
    const float* gq    = (const float*)d_in[3];
    const float* bq    = (const float*)d_in[4];
    const float* Wk    = (const float*)d_in[5];
    const float* gk    = (const float*)d_in[6];
    const float* bk    = (const float*)d_in[7];
    const float* Wproj = (const float*)d_in[8];
    const float* rpb1  = (const float*)d_in[9];
    const float* rpb2  = (const float*)d_in[10];
    const float* Wdy   = (const float*)d_in[11];
    const float* bn_g  = (const float*)d_in[12];
    const float* bn_b  = (const float*)d_in[13];
    float* out = (float*)d_out;

    const int GSMEM   = 2 * GWORDS * 4;                   // 73728
    const int G1SMEM  = 2 * G1WORDS * 4;                  // 108544
    cudaFuncSetAttribute(gemm1_ln_kernel, cudaFuncAttributeMaxDynamicSharedMemorySize, G1SMEM);
    cudaFuncSetAttribute(wgtav_kernel, cudaFuncAttributeMaxDynamicSharedMemorySize, WA_SMEM);
    cudaFuncSetAttribute(mma_gemm_kernel<0>, cudaFuncAttributeMaxDynamicSharedMemorySize, GSMEM);
    cudaFuncSetAttribute(mma_gemm_kernel<1>, cudaFuncAttributeMaxDynamicSharedMemorySize, GSMEM);

    static float *p_kctx = nullptr, *p_kraw = nullptr, *p_mid = nullptr,
                 *p_wqtf = nullptr, *p_wktf = nullptr, *p_wdytf = nullptr;
    static cudaStream_t s1 = nullptr;
    static cudaEvent_t ev0 = nullptr, evW = nullptr, evJoin = nullptr;
    if (!p_kctx) {
        cudaGetSymbolAddress((void**)&p_kctx,  g_kctx);
        cudaGetSymbolAddress((void**)&p_kraw,  g_kraw);
        cudaGetSymbolAddress((void**)&p_mid,   g_mid);
        cudaGetSymbolAddress((void**)&p_wqtf,  g_wqtf);
        cudaGetSymbolAddress((void**)&p_wktf,  g_wktf);
        cudaGetSymbolAddress((void**)&p_wdytf, g_wdytf);
        cudaStreamCreateWithFlags(&s1, cudaStreamNonBlocking);
        cudaEventCreateWithFlags(&ev0,    cudaEventDisableTiming);
        cudaEventCreateWithFlags(&evW,    cudaEventDisableTiming);
        cudaEventCreateWithFlags(&evJoin, cudaEventDisableTiming);
    }

    // fork immediately: pool doesn't need weights
    cudaEventRecord(ev0, 0);
    cudaStreamWaitEvent(s1, ev0, 0);
    pool_kernel<<<dim3(49, NB), 256, 0, s1>>>(ctx);

    // main: weight convert; side chain waits for it before kf GEMM
    wconv_kernel<<<DIMC*DIMC/256, 256>>>(Wq, Wk, Wdy);
    cudaEventRecord(evW, 0);
    cudaStreamWaitEvent(s1, evW, 0);

    mma_gemm_kernel<0><<<dim3(2, 2, 1), 256, GSMEM, s1>>>(p_kctx, p_wktf, p_kraw, nullptr, nullptr, NB*49, 0);
    kfp_kernel<<<dim3(NB*NHEAD, 5), 256, 0, s1>>>(Wproj, gk, bk);
    cudaEventRecord(evJoin, s1);

    // main: gemm1 concurrent with kf chain
    gemm1_ln_kernel<<<dim3(32, 1, NB), 512, G1SMEM>>>(x, p_wqtf, gq, bq);
    cudaStreamWaitEvent(0, evJoin, 0);

    wgtav_kernel<<<dim3(64, 4, NB), 256, WA_SMEM>>>(x, rpb1, rpb2);
    mma_gemm_kernel<1><<<dim3(32, 2, NB), 256, GSMEM>>>(p_mid, p_wdytf, out, bn_g, bn_b, NPOS, NPOS*DIMC);
}